// round 1
// baseline (speedup 1.0000x reference)
#include <cuda_runtime.h>
#include <math.h>

#define BB 4
#define TT 2048
#define CC 1024
#define HH 16
#define DHH 64
#define DFF 4096
#define MM (BB*TT)   /* 8192 */

// -------- scratch (device globals; no allocation) --------
__device__ float g_xn [(size_t)MM*CC];
__device__ float g_qkv[3ull*MM*CC];
__device__ float g_o  [(size_t)MM*CC];
__device__ float g_x1 [(size_t)MM*CC];
__device__ float g_xn2[(size_t)MM*CC];
__device__ float g_ffn[(size_t)MM*DFF];

// ======================= LayerNorm =======================
__global__ void ln_kernel(const float* __restrict__ X, const float* __restrict__ gam,
                          const float* __restrict__ bet, float* __restrict__ Y) {
    int row = blockIdx.x;
    const float* xr = X + (size_t)row * CC;
    int tid = threadIdx.x;
    float4 v = *(const float4*)(xr + tid * 4);
    float s  = v.x + v.y + v.z + v.w;
    float ss = v.x*v.x + v.y*v.y + v.z*v.z + v.w*v.w;
    #pragma unroll
    for (int off = 16; off >= 1; off >>= 1) {
        s  += __shfl_xor_sync(0xffffffffu, s,  off);
        ss += __shfl_xor_sync(0xffffffffu, ss, off);
    }
    __shared__ float sb[8], ssb[8];
    if ((tid & 31) == 0) { sb[tid >> 5] = s; ssb[tid >> 5] = ss; }
    __syncthreads();
    s = 0.f; ss = 0.f;
    #pragma unroll
    for (int w = 0; w < 8; w++) { s += sb[w]; ss += ssb[w]; }
    float mu  = s * (1.0f / CC);
    float var = ss * (1.0f / CC) - mu * mu;
    float rs  = rsqrtf(var + 1e-5f);
    float4 gv = *(const float4*)(gam + tid * 4);
    float4 bv = *(const float4*)(bet + tid * 4);
    float4 o;
    o.x = (v.x - mu) * rs * gv.x + bv.x;
    o.y = (v.y - mu) * rs * gv.y + bv.y;
    o.z = (v.z - mu) * rs * gv.z + bv.z;
    o.w = (v.w - mu) * rs * gv.w + bv.w;
    *(float4*)(Y + (size_t)row * CC + tid * 4) = o;
}

// ============== generic 128x128x8 fp32 SGEMM ==============
// A[M,K] row-major, B[K,N] row-major, C[M,N] row-major.
// C = A*B + bias[n] (+ resid[m,n]) (relu)
template<bool RELU, bool RESID>
__global__ void gemm128(const float* __restrict__ A, const float* __restrict__ B,
                        const float* __restrict__ bias, const float* __restrict__ resid,
                        float* __restrict__ C, int M, int N, int K) {
    __shared__ float As[8][128];
    __shared__ float Bs[8][128];
    int tid = threadIdx.x;
    int m0 = blockIdx.y * 128, n0 = blockIdx.x * 128;
    int arow = tid >> 1,  ac4 = (tid & 1) * 4;
    int brow = tid >> 5,  bc4 = (tid & 31) * 4;
    int ty = tid >> 4, tx = tid & 15;
    float acc[8][8];
    #pragma unroll
    for (int i = 0; i < 8; i++)
        #pragma unroll
        for (int j = 0; j < 8; j++) acc[i][j] = 0.f;

    const float* Ap = A + (size_t)(m0 + arow) * K + ac4;
    const float* Bp = B + (size_t)brow * N + n0 + bc4;

    for (int k0 = 0; k0 < K; k0 += 8) {
        float4 av = *(const float4*)(Ap + k0);
        float4 bv = *(const float4*)(Bp + (size_t)k0 * N);
        As[ac4+0][arow] = av.x; As[ac4+1][arow] = av.y;
        As[ac4+2][arow] = av.z; As[ac4+3][arow] = av.w;
        *(float4*)&Bs[brow][bc4] = bv;
        __syncthreads();
        #pragma unroll
        for (int k = 0; k < 8; k++) {
            float rA[8], rB[8];
            *(float4*)(rA)   = *(const float4*)&As[k][ty*8];
            *(float4*)(rA+4) = *(const float4*)&As[k][ty*8+4];
            *(float4*)(rB)   = *(const float4*)&Bs[k][tx*8];
            *(float4*)(rB+4) = *(const float4*)&Bs[k][tx*8+4];
            #pragma unroll
            for (int i = 0; i < 8; i++)
                #pragma unroll
                for (int j = 0; j < 8; j++)
                    acc[i][j] = fmaf(rA[i], rB[j], acc[i][j]);
        }
        __syncthreads();
    }
    #pragma unroll
    for (int i = 0; i < 8; i++) {
        size_t m = (size_t)(m0 + ty*8 + i);
        #pragma unroll
        for (int j = 0; j < 8; j++) {
            int n = n0 + tx*8 + j;
            float v = acc[i][j] + bias[n];
            if (RESID) v += resid[m * N + n];
            if (RELU)  v = fmaxf(v, 0.f);
            C[m * N + n] = v;
        }
    }
}

// ====== fused QKV GEMM: xn[8192,1024] x virtual W[1024,3072] ======
// n in [0,3072): mat = n/1024, h = (n%1024)/64, d = n%64
// W element = Wmat[h*C*DH + k*DH + d].  Output: g_qkv[mat][m][h*64+d]
__global__ void gemm_qkv(const float* __restrict__ A,
                         const float* __restrict__ Wq, const float* __restrict__ Wk,
                         const float* __restrict__ Wv,
                         const float* __restrict__ bq, const float* __restrict__ bk,
                         const float* __restrict__ bv_, float* __restrict__ out) {
    const int K = CC;
    __shared__ float As[8][128];
    __shared__ float Bs[8][128];
    int tid = threadIdx.x;
    int m0 = blockIdx.y * 128, n0 = blockIdx.x * 128;
    int mat  = n0 >> 10;
    int rem0 = n0 & 1023;
    const float* W  = (mat == 0) ? Wq : (mat == 1) ? Wk : Wv;
    const float* bb = (mat == 0) ? bq : (mat == 1) ? bk : bv_;

    int arow = tid >> 1,  ac4 = (tid & 1) * 4;
    int brow = tid >> 5,  bc4 = (tid & 31) * 4;
    int ty = tid >> 4, tx = tid & 15;
    float acc[8][8];
    #pragma unroll
    for (int i = 0; i < 8; i++)
        #pragma unroll
        for (int j = 0; j < 8; j++) acc[i][j] = 0.f;

    const float* Ap = A + (size_t)(m0 + arow) * K + ac4;
    int nb = rem0 + bc4;
    int hh = nb >> 6, dd = nb & 63;
    const float* Wp = W + ((size_t)hh << 16) + (size_t)brow * DHH + dd; // h*C*DH=h*65536

    for (int k0 = 0; k0 < K; k0 += 8) {
        float4 av = *(const float4*)(Ap + k0);
        float4 bvv = *(const float4*)(Wp + (size_t)k0 * DHH);
        As[ac4+0][arow] = av.x; As[ac4+1][arow] = av.y;
        As[ac4+2][arow] = av.z; As[ac4+3][arow] = av.w;
        *(float4*)&Bs[brow][bc4] = bvv;
        __syncthreads();
        #pragma unroll
        for (int k = 0; k < 8; k++) {
            float rA[8], rB[8];
            *(float4*)(rA)   = *(const float4*)&As[k][ty*8];
            *(float4*)(rA+4) = *(const float4*)&As[k][ty*8+4];
            *(float4*)(rB)   = *(const float4*)&Bs[k][tx*8];
            *(float4*)(rB+4) = *(const float4*)&Bs[k][tx*8+4];
            #pragma unroll
            for (int i = 0; i < 8; i++)
                #pragma unroll
                for (int j = 0; j < 8; j++)
                    acc[i][j] = fmaf(rA[i], rB[j], acc[i][j]);
        }
        __syncthreads();
    }
    float* Co = out + ((size_t)mat << 23);  // mat * 8192*1024
    #pragma unroll
    for (int i = 0; i < 8; i++) {
        size_t m = (size_t)(m0 + ty*8 + i);
        #pragma unroll
        for (int j = 0; j < 8; j++) {
            int n = rem0 + tx*8 + j;
            Co[m * CC + n] = acc[i][j] + bb[n];
        }
    }
}

// ================= flash attention (fp32) =================
// grid (T/64, H, B), 256 threads. BR=BC=64, DH=64.
// scores = (Q.K^T) * 8  (reference multiplies by sqrt(DH))
#define APITCH 68
__global__ void attn_kernel(const float* __restrict__ Q, const float* __restrict__ Km,
                            const float* __restrict__ V, float* __restrict__ O) {
    extern __shared__ float smem[];
    float (*Qs)[APITCH] = (float(*)[APITCH])(smem);
    float (*Ks)[APITCH] = (float(*)[APITCH])(smem + 64*APITCH);
    float (*Vs)[APITCH] = (float(*)[APITCH])(smem + 2*64*APITCH);
    float (*Ps)[APITCH] = (float(*)[APITCH])(smem + 3*64*APITCH);

    int r0 = blockIdx.x * 64;
    int h  = blockIdx.y;
    int b  = blockIdx.z;
    size_t base = (size_t)b * TT * CC + h * DHH;  // + t*CC + d
    int tid = threadIdx.x, ty = tid >> 4, tx = tid & 15;

    // load Q tile
    {
        int lr = tid >> 4, c4 = (tid & 15) * 4;
        #pragma unroll
        for (int p = 0; p < 4; p++) {
            int row = p * 16 + lr;
            *(float4*)&Qs[row][c4] =
                *(const float4*)(Q + base + (size_t)(r0 + row) * CC + c4);
        }
    }
    float acc[4][4];
    #pragma unroll
    for (int i = 0; i < 4; i++)
        #pragma unroll
        for (int j = 0; j < 4; j++) acc[i][j] = 0.f;
    float mrow[4] = {-3e38f, -3e38f, -3e38f, -3e38f};
    float lrow[4] = {0.f, 0.f, 0.f, 0.f};

    for (int s0 = 0; s0 < TT; s0 += 64) {
        __syncthreads();   // previous tile fully consumed
        {
            int lr = tid >> 4, c4 = (tid & 15) * 4;
            #pragma unroll
            for (int p = 0; p < 4; p++) {
                int row = p * 16 + lr;
                size_t g = base + (size_t)(s0 + row) * CC + c4;
                *(float4*)&Ks[row][c4] = *(const float4*)(Km + g);
                *(float4*)&Vs[row][c4] = *(const float4*)(V + g);
            }
        }
        __syncthreads();

        // S = Q * K^T
        float sv[4][4];
        #pragma unroll
        for (int i = 0; i < 4; i++)
            #pragma unroll
            for (int j = 0; j < 4; j++) sv[i][j] = 0.f;
        #pragma unroll
        for (int d4 = 0; d4 < 16; d4++) {
            float4 qr[4], kr[4];
            #pragma unroll
            for (int i = 0; i < 4; i++) qr[i] = *(const float4*)&Qs[ty*4 + i][d4*4];
            #pragma unroll
            for (int j = 0; j < 4; j++) kr[j] = *(const float4*)&Ks[tx + 16*j][d4*4];
            #pragma unroll
            for (int i = 0; i < 4; i++)
                #pragma unroll
                for (int j = 0; j < 4; j++) {
                    sv[i][j] = fmaf(qr[i].x, kr[j].x, sv[i][j]);
                    sv[i][j] = fmaf(qr[i].y, kr[j].y, sv[i][j]);
                    sv[i][j] = fmaf(qr[i].z, kr[j].z, sv[i][j]);
                    sv[i][j] = fmaf(qr[i].w, kr[j].w, sv[i][j]);
                }
        }
        // online softmax (scale = *8)
        #pragma unroll
        for (int i = 0; i < 4; i++) {
            #pragma unroll
            for (int j = 0; j < 4; j++) sv[i][j] *= 8.0f;
            float mt = fmaxf(fmaxf(sv[i][0], sv[i][1]), fmaxf(sv[i][2], sv[i][3]));
            #pragma unroll
            for (int off = 8; off >= 1; off >>= 1)
                mt = fmaxf(mt, __shfl_xor_sync(0xffffffffu, mt, off, 16));
            float mnew  = fmaxf(mrow[i], mt);
            float alpha = __expf(mrow[i] - mnew);
            float psum  = 0.f;
            #pragma unroll
            for (int j = 0; j < 4; j++) {
                float p = __expf(sv[i][j] - mnew);
                Ps[ty*4 + i][tx + 16*j] = p;
                psum += p;
            }
            #pragma unroll
            for (int off = 8; off >= 1; off >>= 1)
                psum += __shfl_xor_sync(0xffffffffu, psum, off, 16);
            lrow[i] = lrow[i] * alpha + psum;
            mrow[i] = mnew;
            #pragma unroll
            for (int j = 0; j < 4; j++) acc[i][j] *= alpha;
        }
        __syncthreads();
        // O += P * V
        #pragma unroll 4
        for (int k = 0; k < 64; k++) {
            float pv[4], vv[4];
            #pragma unroll
            for (int i = 0; i < 4; i++) pv[i] = Ps[ty*4 + i][k];
            #pragma unroll
            for (int j = 0; j < 4; j++) vv[j] = Vs[k][tx + 16*j];
            #pragma unroll
            for (int i = 0; i < 4; i++)
                #pragma unroll
                for (int j = 0; j < 4; j++)
                    acc[i][j] = fmaf(pv[i], vv[j], acc[i][j]);
        }
    }
    // write O (already in [b,t,h*64+d] concat layout)
    #pragma unroll
    for (int i = 0; i < 4; i++) {
        float inv = 1.0f / lrow[i];
        #pragma unroll
        for (int j = 0; j < 4; j++)
            O[base + (size_t)(r0 + ty*4 + i) * CC + tx + 16*j] = acc[i][j] * inv;
    }
}

// ========================= launch =========================
extern "C" void kernel_launch(void* const* d_in, const int* in_sizes, int n_in,
                              void* d_out, int out_size) {
    const float* x     = (const float*)d_in[0];
    const float* Wq    = (const float*)d_in[1];
    const float* bq    = (const float*)d_in[2];
    const float* Wk    = (const float*)d_in[3];
    const float* bk    = (const float*)d_in[4];
    const float* Wv    = (const float*)d_in[5];
    const float* bv    = (const float*)d_in[6];
    const float* Wo    = (const float*)d_in[7];
    const float* bo    = (const float*)d_in[8];
    const float* ln1g  = (const float*)d_in[9];
    const float* ln1b  = (const float*)d_in[10];
    const float* ln2g  = (const float*)d_in[11];
    const float* ln2b  = (const float*)d_in[12];
    const float* W1    = (const float*)d_in[13];
    const float* b1    = (const float*)d_in[14];
    const float* W2    = (const float*)d_in[15];
    const float* b2    = (const float*)d_in[16];
    float* out = (float*)d_out;

    float *xn, *qkv, *o, *x1, *xn2, *ffn;
    cudaGetSymbolAddress((void**)&xn,  g_xn);
    cudaGetSymbolAddress((void**)&qkv, g_qkv);
    cudaGetSymbolAddress((void**)&o,   g_o);
    cudaGetSymbolAddress((void**)&x1,  g_x1);
    cudaGetSymbolAddress((void**)&xn2, g_xn2);
    cudaGetSymbolAddress((void**)&ffn, g_ffn);

    const int ATTN_SMEM = 4 * 64 * APITCH * sizeof(float);  // 69632 B
    cudaFuncSetAttribute(attn_kernel, cudaFuncAttributeMaxDynamicSharedMemorySize, ATTN_SMEM);

    // 1) LN1
    ln_kernel<<<MM, 256>>>(x, ln1g, ln1b, xn);
    // 2) QKV
    gemm_qkv<<<dim3(24, 64), 256>>>(xn, Wq, Wk, Wv, bq, bk, bv, qkv);
    // 3) attention
    attn_kernel<<<dim3(TT/64, HH, BB), 256, ATTN_SMEM>>>(
        qkv, qkv + (1ull << 23), qkv + (2ull << 23), o);
    // 4) out proj + residual
    gemm128<false, true><<<dim3(8, 64), 256>>>(o, Wo, bo, x, x1, MM, CC, CC);
    // 5) LN2
    ln_kernel<<<MM, 256>>>(x1, ln2g, ln2b, xn2);
    // 6) FFN1 (relu)
    gemm128<true, false><<<dim3(32, 64), 256>>>(xn2, W1, b1, nullptr, ffn, MM, DFF, CC);
    // 7) FFN2 + residual -> out
    gemm128<false, true><<<dim3(8, 64), 256>>>(ffn, W2, b2, x1, out, MM, CC, DFF);
}

// round 2
// speedup vs baseline: 1.0005x; 1.0005x over previous
#include <cuda_runtime.h>
#include <math.h>

#define BB 4
#define TT 2048
#define CC 1024
#define HH 16
#define DHH 64
#define DFF 4096
#define MM (BB*TT)   /* 8192 */

// -------- scratch (device globals; no allocation) --------
__device__ float g_xn [(size_t)MM*CC];
__device__ float g_qkv[3ull*MM*CC];
__device__ float g_o  [(size_t)MM*CC];
__device__ float g_x1 [(size_t)MM*CC];
__device__ float g_xn2[(size_t)MM*CC];
__device__ float g_ffn[(size_t)MM*DFF];

// ======================= LayerNorm =======================
__global__ void ln_kernel(const float* __restrict__ X, const float* __restrict__ gam,
                          const float* __restrict__ bet, float* __restrict__ Y) {
    int row = blockIdx.x;
    const float* xr = X + (size_t)row * CC;
    int tid = threadIdx.x;
    float4 v = *(const float4*)(xr + tid * 4);
    float s  = v.x + v.y + v.z + v.w;
    float ss = v.x*v.x + v.y*v.y + v.z*v.z + v.w*v.w;
    #pragma unroll
    for (int off = 16; off >= 1; off >>= 1) {
        s  += __shfl_xor_sync(0xffffffffu, s,  off);
        ss += __shfl_xor_sync(0xffffffffu, ss, off);
    }
    __shared__ float sb[8], ssb[8];
    if ((tid & 31) == 0) { sb[tid >> 5] = s; ssb[tid >> 5] = ss; }
    __syncthreads();
    s = 0.f; ss = 0.f;
    #pragma unroll
    for (int w = 0; w < 8; w++) { s += sb[w]; ss += ssb[w]; }
    float mu  = s * (1.0f / CC);
    float var = ss * (1.0f / CC) - mu * mu;
    float rs  = rsqrtf(var + 1e-5f);
    float4 gv = *(const float4*)(gam + tid * 4);
    float4 bv = *(const float4*)(bet + tid * 4);
    float4 o;
    o.x = (v.x - mu) * rs * gv.x + bv.x;
    o.y = (v.y - mu) * rs * gv.y + bv.y;
    o.z = (v.z - mu) * rs * gv.z + bv.z;
    o.w = (v.w - mu) * rs * gv.w + bv.w;
    *(float4*)(Y + (size_t)row * CC + tid * 4) = o;
}

// ============== generic 128x128x8 fp32 SGEMM ==============
// A[M,K] row-major, B[K,N] row-major, C[M,N] row-major.
// C = A*B + bias[n] (+ resid[m,n]) (relu)
template<bool RELU, bool RESID>
__global__ void gemm128(const float* __restrict__ A, const float* __restrict__ B,
                        const float* __restrict__ bias, const float* __restrict__ resid,
                        float* __restrict__ C, int M, int N, int K) {
    __shared__ float As[8][128];
    __shared__ float Bs[8][128];
    int tid = threadIdx.x;
    int m0 = blockIdx.y * 128, n0 = blockIdx.x * 128;
    int arow = tid >> 1,  ac4 = (tid & 1) * 4;
    int brow = tid >> 5,  bc4 = (tid & 31) * 4;
    int ty = tid >> 4, tx = tid & 15;
    float acc[8][8];
    #pragma unroll
    for (int i = 0; i < 8; i++)
        #pragma unroll
        for (int j = 0; j < 8; j++) acc[i][j] = 0.f;

    const float* Ap = A + (size_t)(m0 + arow) * K + ac4;
    const float* Bp = B + (size_t)brow * N + n0 + bc4;

    for (int k0 = 0; k0 < K; k0 += 8) {
        float4 av = *(const float4*)(Ap + k0);
        float4 bv = *(const float4*)(Bp + (size_t)k0 * N);
        As[ac4+0][arow] = av.x; As[ac4+1][arow] = av.y;
        As[ac4+2][arow] = av.z; As[ac4+3][arow] = av.w;
        *(float4*)&Bs[brow][bc4] = bv;
        __syncthreads();
        #pragma unroll
        for (int k = 0; k < 8; k++) {
            float rA[8], rB[8];
            *(float4*)(rA)   = *(const float4*)&As[k][ty*8];
            *(float4*)(rA+4) = *(const float4*)&As[k][ty*8+4];
            *(float4*)(rB)   = *(const float4*)&Bs[k][tx*8];
            *(float4*)(rB+4) = *(const float4*)&Bs[k][tx*8+4];
            #pragma unroll
            for (int i = 0; i < 8; i++)
                #pragma unroll
                for (int j = 0; j < 8; j++)
                    acc[i][j] = fmaf(rA[i], rB[j], acc[i][j]);
        }
        __syncthreads();
    }
    #pragma unroll
    for (int i = 0; i < 8; i++) {
        size_t m = (size_t)(m0 + ty*8 + i);
        #pragma unroll
        for (int j = 0; j < 8; j++) {
            int n = n0 + tx*8 + j;
            float v = acc[i][j] + bias[n];
            if (RESID) v += resid[m * N + n];
            if (RELU)  v = fmaxf(v, 0.f);
            C[m * N + n] = v;
        }
    }
}

// ====== fused QKV GEMM: xn[8192,1024] x virtual W[1024,3072] ======
// n in [0,3072): mat = n/1024, h = (n%1024)/64, d = n%64
// W element = Wmat[h*C*DH + k*DH + d].  Output: g_qkv[mat][m][h*64+d]
__global__ void gemm_qkv(const float* __restrict__ A,
                         const float* __restrict__ Wq, const float* __restrict__ Wk,
                         const float* __restrict__ Wv,
                         const float* __restrict__ bq, const float* __restrict__ bk,
                         const float* __restrict__ bv_, float* __restrict__ out) {
    const int K = CC;
    __shared__ float As[8][128];
    __shared__ float Bs[8][128];
    int tid = threadIdx.x;
    int m0 = blockIdx.y * 128, n0 = blockIdx.x * 128;
    int mat  = n0 >> 10;
    int rem0 = n0 & 1023;
    const float* W  = (mat == 0) ? Wq : (mat == 1) ? Wk : Wv;
    const float* bb = (mat == 0) ? bq : (mat == 1) ? bk : bv_;

    int arow = tid >> 1,  ac4 = (tid & 1) * 4;
    int brow = tid >> 5,  bc4 = (tid & 31) * 4;
    int ty = tid >> 4, tx = tid & 15;
    float acc[8][8];
    #pragma unroll
    for (int i = 0; i < 8; i++)
        #pragma unroll
        for (int j = 0; j < 8; j++) acc[i][j] = 0.f;

    const float* Ap = A + (size_t)(m0 + arow) * K + ac4;
    int nb = rem0 + bc4;
    int hh = nb >> 6, dd = nb & 63;
    const float* Wp = W + ((size_t)hh << 16) + (size_t)brow * DHH + dd; // h*C*DH=h*65536

    for (int k0 = 0; k0 < K; k0 += 8) {
        float4 av = *(const float4*)(Ap + k0);
        float4 bvv = *(const float4*)(Wp + (size_t)k0 * DHH);
        As[ac4+0][arow] = av.x; As[ac4+1][arow] = av.y;
        As[ac4+2][arow] = av.z; As[ac4+3][arow] = av.w;
        *(float4*)&Bs[brow][bc4] = bvv;
        __syncthreads();
        #pragma unroll
        for (int k = 0; k < 8; k++) {
            float rA[8], rB[8];
            *(float4*)(rA)   = *(const float4*)&As[k][ty*8];
            *(float4*)(rA+4) = *(const float4*)&As[k][ty*8+4];
            *(float4*)(rB)   = *(const float4*)&Bs[k][tx*8];
            *(float4*)(rB+4) = *(const float4*)&Bs[k][tx*8+4];
            #pragma unroll
            for (int i = 0; i < 8; i++)
                #pragma unroll
                for (int j = 0; j < 8; j++)
                    acc[i][j] = fmaf(rA[i], rB[j], acc[i][j]);
        }
        __syncthreads();
    }
    float* Co = out + ((size_t)mat << 23);  // mat * 8192*1024
    #pragma unroll
    for (int i = 0; i < 8; i++) {
        size_t m = (size_t)(m0 + ty*8 + i);
        #pragma unroll
        for (int j = 0; j < 8; j++) {
            int n = rem0 + tx*8 + j;
            Co[m * CC + n] = acc[i][j] + bb[n];
        }
    }
}

// ================= flash attention (fp32) =================
// grid (T/64, H, B), 256 threads. BR=BC=64, DH=64.
// scores = (Q.K^T) * 8  (reference multiplies by sqrt(DH))
#define APITCH 68
__global__ void attn_kernel(const float* __restrict__ Q, const float* __restrict__ Km,
                            const float* __restrict__ V, float* __restrict__ O) {
    extern __shared__ float smem[];
    float (*Qs)[APITCH] = (float(*)[APITCH])(smem);
    float (*Ks)[APITCH] = (float(*)[APITCH])(smem + 64*APITCH);
    float (*Vs)[APITCH] = (float(*)[APITCH])(smem + 2*64*APITCH);
    float (*Ps)[APITCH] = (float(*)[APITCH])(smem + 3*64*APITCH);

    int r0 = blockIdx.x * 64;
    int h  = blockIdx.y;
    int b  = blockIdx.z;
    size_t base = (size_t)b * TT * CC + h * DHH;  // + t*CC + d
    int tid = threadIdx.x, ty = tid >> 4, tx = tid & 15;

    // load Q tile
    {
        int lr = tid >> 4, c4 = (tid & 15) * 4;
        #pragma unroll
        for (int p = 0; p < 4; p++) {
            int row = p * 16 + lr;
            *(float4*)&Qs[row][c4] =
                *(const float4*)(Q + base + (size_t)(r0 + row) * CC + c4);
        }
    }
    float acc[4][4];
    #pragma unroll
    for (int i = 0; i < 4; i++)
        #pragma unroll
        for (int j = 0; j < 4; j++) acc[i][j] = 0.f;
    float mrow[4] = {-3e38f, -3e38f, -3e38f, -3e38f};
    float lrow[4] = {0.f, 0.f, 0.f, 0.f};

    for (int s0 = 0; s0 < TT; s0 += 64) {
        __syncthreads();   // previous tile fully consumed
        {
            int lr = tid >> 4, c4 = (tid & 15) * 4;
            #pragma unroll
            for (int p = 0; p < 4; p++) {
                int row = p * 16 + lr;
                size_t g = base + (size_t)(s0 + row) * CC + c4;
                *(float4*)&Ks[row][c4] = *(const float4*)(Km + g);
                *(float4*)&Vs[row][c4] = *(const float4*)(V + g);
            }
        }
        __syncthreads();

        // S = Q * K^T
        float sv[4][4];
        #pragma unroll
        for (int i = 0; i < 4; i++)
            #pragma unroll
            for (int j = 0; j < 4; j++) sv[i][j] = 0.f;
        #pragma unroll
        for (int d4 = 0; d4 < 16; d4++) {
            float4 qr[4], kr[4];
            #pragma unroll
            for (int i = 0; i < 4; i++) qr[i] = *(const float4*)&Qs[ty*4 + i][d4*4];
            #pragma unroll
            for (int j = 0; j < 4; j++) kr[j] = *(const float4*)&Ks[tx + 16*j][d4*4];
            #pragma unroll
            for (int i = 0; i < 4; i++)
                #pragma unroll
                for (int j = 0; j < 4; j++) {
                    sv[i][j] = fmaf(qr[i].x, kr[j].x, sv[i][j]);
                    sv[i][j] = fmaf(qr[i].y, kr[j].y, sv[i][j]);
                    sv[i][j] = fmaf(qr[i].z, kr[j].z, sv[i][j]);
                    sv[i][j] = fmaf(qr[i].w, kr[j].w, sv[i][j]);
                }
        }
        // online softmax (scale = *8)
        #pragma unroll
        for (int i = 0; i < 4; i++) {
            #pragma unroll
            for (int j = 0; j < 4; j++) sv[i][j] *= 8.0f;
            float mt = fmaxf(fmaxf(sv[i][0], sv[i][1]), fmaxf(sv[i][2], sv[i][3]));
            #pragma unroll
            for (int off = 8; off >= 1; off >>= 1)
                mt = fmaxf(mt, __shfl_xor_sync(0xffffffffu, mt, off, 16));
            float mnew  = fmaxf(mrow[i], mt);
            float alpha = __expf(mrow[i] - mnew);
            float psum  = 0.f;
            #pragma unroll
            for (int j = 0; j < 4; j++) {
                float p = __expf(sv[i][j] - mnew);
                Ps[ty*4 + i][tx + 16*j] = p;
                psum += p;
            }
            #pragma unroll
            for (int off = 8; off >= 1; off >>= 1)
                psum += __shfl_xor_sync(0xffffffffu, psum, off, 16);
            lrow[i] = lrow[i] * alpha + psum;
            mrow[i] = mnew;
            #pragma unroll
            for (int j = 0; j < 4; j++) acc[i][j] *= alpha;
        }
        __syncthreads();
        // O += P * V
        #pragma unroll 4
        for (int k = 0; k < 64; k++) {
            float pv[4], vv[4];
            #pragma unroll
            for (int i = 0; i < 4; i++) pv[i] = Ps[ty*4 + i][k];
            #pragma unroll
            for (int j = 0; j < 4; j++) vv[j] = Vs[k][tx + 16*j];
            #pragma unroll
            for (int i = 0; i < 4; i++)
                #pragma unroll
                for (int j = 0; j < 4; j++)
                    acc[i][j] = fmaf(pv[i], vv[j], acc[i][j]);
        }
    }
    // write O (already in [b,t,h*64+d] concat layout)
    #pragma unroll
    for (int i = 0; i < 4; i++) {
        float inv = 1.0f / lrow[i];
        #pragma unroll
        for (int j = 0; j < 4; j++)
            O[base + (size_t)(r0 + ty*4 + i) * CC + tx + 16*j] = acc[i][j] * inv;
    }
}

// ========================= launch =========================
extern "C" void kernel_launch(void* const* d_in, const int* in_sizes, int n_in,
                              void* d_out, int out_size) {
    const float* x     = (const float*)d_in[0];
    const float* Wq    = (const float*)d_in[1];
    const float* bq    = (const float*)d_in[2];
    const float* Wk    = (const float*)d_in[3];
    const float* bk    = (const float*)d_in[4];
    const float* Wv    = (const float*)d_in[5];
    const float* bv    = (const float*)d_in[6];
    const float* Wo    = (const float*)d_in[7];
    const float* bo    = (const float*)d_in[8];
    const float* ln1g  = (const float*)d_in[9];
    const float* ln1b  = (const float*)d_in[10];
    const float* ln2g  = (const float*)d_in[11];
    const float* ln2b  = (const float*)d_in[12];
    const float* W1    = (const float*)d_in[13];
    const float* b1    = (const float*)d_in[14];
    const float* W2    = (const float*)d_in[15];
    const float* b2    = (const float*)d_in[16];
    float* out = (float*)d_out;

    float *xn, *qkv, *o, *x1, *xn2, *ffn;
    cudaGetSymbolAddress((void**)&xn,  g_xn);
    cudaGetSymbolAddress((void**)&qkv, g_qkv);
    cudaGetSymbolAddress((void**)&o,   g_o);
    cudaGetSymbolAddress((void**)&x1,  g_x1);
    cudaGetSymbolAddress((void**)&xn2, g_xn2);
    cudaGetSymbolAddress((void**)&ffn, g_ffn);

    const int ATTN_SMEM = 4 * 64 * APITCH * sizeof(float);  // 69632 B
    cudaFuncSetAttribute(attn_kernel, cudaFuncAttributeMaxDynamicSharedMemorySize, ATTN_SMEM);

    // 1) LN1
    ln_kernel<<<MM, 256>>>(x, ln1g, ln1b, xn);
    // 2) QKV
    gemm_qkv<<<dim3(24, 64), 256>>>(xn, Wq, Wk, Wv, bq, bk, bv, qkv);
    // 3) attention
    attn_kernel<<<dim3(TT/64, HH, BB), 256, ATTN_SMEM>>>(
        qkv, qkv + (1ull << 23), qkv + (2ull << 23), o);
    // 4) out proj + residual
    gemm128<false, true><<<dim3(8, 64), 256>>>(o, Wo, bo, x, x1, MM, CC, CC);
    // 5) LN2
    ln_kernel<<<MM, 256>>>(x1, ln2g, ln2b, xn2);
    // 6) FFN1 (relu)
    gemm128<true, false><<<dim3(32, 64), 256>>>(xn2, W1, b1, nullptr, ffn, MM, DFF, CC);
    // 7) FFN2 + residual -> out
    gemm128<false, true><<<dim3(8, 64), 256>>>(ffn, W2, b2, x1, out, MM, CC, DFF);
}

// round 3
// speedup vs baseline: 1.5531x; 1.5522x over previous
#include <cuda_runtime.h>
#include <math.h>
#include <stdint.h>

#define BB 4
#define TT 2048
#define CC 1024
#define HH 16
#define DHH 64
#define DFF 4096
#define MM (BB*TT)   /* 8192 */

// -------- scratch (device globals; no allocation) --------
__device__ float g_xn [(size_t)MM*CC];
__device__ float g_qkv[3ull*MM*CC];
__device__ float g_o  [(size_t)MM*CC];
__device__ float g_x1 [(size_t)MM*CC];
__device__ float g_xn2[(size_t)MM*CC];
__device__ float g_ffn[(size_t)MM*DFF];

// ======================= helpers =======================
__device__ __forceinline__ uint32_t f2tf(float f) {
    uint32_t u;
    asm("cvt.rna.tf32.f32 %0, %1;" : "=r"(u) : "f"(f));
    return u;
}
__device__ __forceinline__ void split_tf(float f, uint32_t& hi, uint32_t& lo) {
    hi = f2tf(f);
    lo = f2tf(f - __uint_as_float(hi));
}

#define MMA_TF32(d, a, b) \
    asm volatile("mma.sync.aligned.m16n8k8.row.col.f32.tf32.tf32.f32 " \
        "{%0,%1,%2,%3}, {%4,%5,%6,%7}, {%8,%9}, {%0,%1,%2,%3};" \
        : "+f"(d[0]), "+f"(d[1]), "+f"(d[2]), "+f"(d[3]) \
        : "r"(a[0]), "r"(a[1]), "r"(a[2]), "r"(a[3]), "r"(b[0]), "r"(b[1]))

// ======================= LayerNorm =======================
__global__ void ln_kernel(const float* __restrict__ X, const float* __restrict__ gam,
                          const float* __restrict__ bet, float* __restrict__ Y) {
    int row = blockIdx.x;
    const float* xr = X + (size_t)row * CC;
    int tid = threadIdx.x;
    float4 v = *(const float4*)(xr + tid * 4);
    float s  = v.x + v.y + v.z + v.w;
    float ss = v.x*v.x + v.y*v.y + v.z*v.z + v.w*v.w;
    #pragma unroll
    for (int off = 16; off >= 1; off >>= 1) {
        s  += __shfl_xor_sync(0xffffffffu, s,  off);
        ss += __shfl_xor_sync(0xffffffffu, ss, off);
    }
    __shared__ float sb[8], ssb[8];
    if ((tid & 31) == 0) { sb[tid >> 5] = s; ssb[tid >> 5] = ss; }
    __syncthreads();
    s = 0.f; ss = 0.f;
    #pragma unroll
    for (int w = 0; w < 8; w++) { s += sb[w]; ss += ssb[w]; }
    float mu  = s * (1.0f / CC);
    float var = ss * (1.0f / CC) - mu * mu;
    float rs  = rsqrtf(var + 1e-5f);
    float4 gv = *(const float4*)(gam + tid * 4);
    float4 bv = *(const float4*)(bet + tid * 4);
    float4 o;
    o.x = (v.x - mu) * rs * gv.x + bv.x;
    o.y = (v.y - mu) * rs * gv.y + bv.y;
    o.z = (v.z - mu) * rs * gv.z + bv.z;
    o.w = (v.w - mu) * rs * gv.w + bv.w;
    *(float4*)(Y + (size_t)row * CC + tid * 4) = o;
}

// ============ tf32 tensor-core GEMM, 128x128 tile, K-step 16 ============
// A[M,K] row-major, B[K,N] row-major. C = A*B + bias (+resid) (relu).
#define APAD 20
#define BPAD 136

template<bool RELU, bool RESID>
__global__ void gemm_tc(const float* __restrict__ A, const float* __restrict__ B,
                        const float* __restrict__ bias, const float* __restrict__ resid,
                        float* __restrict__ C, int M, int N, int K) {
    __shared__ uint32_t As[128][APAD];
    __shared__ uint32_t Bs[16][BPAD];
    int tid = threadIdx.x;
    int m0 = blockIdx.y * 128, n0 = blockIdx.x * 128;
    int lane = tid & 31, warp = tid >> 5;
    int wy = warp >> 2, wx = warp & 3;            // warp tile origin (wy*64, wx*32)
    int lr = lane >> 2, lc = lane & 3;

    float acc[4][4][4];
    #pragma unroll
    for (int i = 0; i < 4; i++)
        #pragma unroll
        for (int j = 0; j < 4; j++)
            #pragma unroll
            for (int f = 0; f < 4; f++) acc[i][j][f] = 0.f;

    int ar = tid >> 2, ak4 = (tid & 3) * 4;       // A loader: rows ar, ar+64
    int bk = tid >> 5, bn4 = (tid & 31) * 4;      // B loader: rows bk, bk+8
    const float* Ap0 = A + (size_t)(m0 + ar) * K + ak4;
    const float* Ap1 = A + (size_t)(m0 + ar + 64) * K + ak4;
    const float* Bp  = B + (size_t)bk * N + n0 + bn4;

    for (int k0 = 0; k0 < K; k0 += 16) {
        float4 av0 = *(const float4*)(Ap0 + k0);
        float4 av1 = *(const float4*)(Ap1 + k0);
        float4 bv0 = *(const float4*)(Bp + (size_t)k0 * N);
        float4 bv1 = *(const float4*)(Bp + (size_t)(k0 + 8) * N);
        As[ar][ak4+0] = f2tf(av0.x); As[ar][ak4+1] = f2tf(av0.y);
        As[ar][ak4+2] = f2tf(av0.z); As[ar][ak4+3] = f2tf(av0.w);
        As[ar+64][ak4+0] = f2tf(av1.x); As[ar+64][ak4+1] = f2tf(av1.y);
        As[ar+64][ak4+2] = f2tf(av1.z); As[ar+64][ak4+3] = f2tf(av1.w);
        Bs[bk][bn4+0] = f2tf(bv0.x); Bs[bk][bn4+1] = f2tf(bv0.y);
        Bs[bk][bn4+2] = f2tf(bv0.z); Bs[bk][bn4+3] = f2tf(bv0.w);
        Bs[bk+8][bn4+0] = f2tf(bv1.x); Bs[bk+8][bn4+1] = f2tf(bv1.y);
        Bs[bk+8][bn4+2] = f2tf(bv1.z); Bs[bk+8][bn4+3] = f2tf(bv1.w);
        __syncthreads();
        #pragma unroll
        for (int ks = 0; ks < 2; ks++) {
            int kk = ks * 8 + lc;
            uint32_t af[4][4], bf[4][2];
            #pragma unroll
            for (int mi = 0; mi < 4; mi++) {
                int mrow = wy*64 + mi*16 + lr;
                af[mi][0] = As[mrow][kk];
                af[mi][1] = As[mrow+8][kk];
                af[mi][2] = As[mrow][kk+4];
                af[mi][3] = As[mrow+8][kk+4];
            }
            #pragma unroll
            for (int nj = 0; nj < 4; nj++) {
                int nc = wx*32 + nj*8 + lr;
                bf[nj][0] = Bs[ks*8 + lc][nc];
                bf[nj][1] = Bs[ks*8 + 4 + lc][nc];
            }
            #pragma unroll
            for (int mi = 0; mi < 4; mi++)
                #pragma unroll
                for (int nj = 0; nj < 4; nj++)
                    MMA_TF32(acc[mi][nj], af[mi], bf[nj]);
        }
        __syncthreads();
    }
    // epilogue
    #pragma unroll
    for (int mi = 0; mi < 4; mi++) {
        #pragma unroll
        for (int nj = 0; nj < 4; nj++) {
            int row = m0 + wy*64 + mi*16 + lr;
            int col = n0 + wx*32 + nj*8 + 2*lc;
            float b0 = bias[col], b1 = bias[col+1];
            float2 v0 = make_float2(acc[mi][nj][0] + b0, acc[mi][nj][1] + b1);
            float2 v1 = make_float2(acc[mi][nj][2] + b0, acc[mi][nj][3] + b1);
            if (RESID) {
                float2 r0 = *(const float2*)(resid + (size_t)row * N + col);
                float2 r1 = *(const float2*)(resid + (size_t)(row+8) * N + col);
                v0.x += r0.x; v0.y += r0.y; v1.x += r1.x; v1.y += r1.y;
            }
            if (RELU) {
                v0.x = fmaxf(v0.x, 0.f); v0.y = fmaxf(v0.y, 0.f);
                v1.x = fmaxf(v1.x, 0.f); v1.y = fmaxf(v1.y, 0.f);
            }
            *(float2*)(C + (size_t)row * N + col) = v0;
            *(float2*)(C + (size_t)(row+8) * N + col) = v1;
        }
    }
}

// ============ fused QKV GEMM, 3xTF32 (fp32-accurate) ============
// Virtual B[K=1024, N=3072]: n -> (mat, h, d); element = Wmat[h*C*DH + k*DH + d]
__global__ void gemm_qkv_tc(const float* __restrict__ A,
                            const float* __restrict__ Wq, const float* __restrict__ Wk,
                            const float* __restrict__ Wv,
                            const float* __restrict__ bq, const float* __restrict__ bk_,
                            const float* __restrict__ bv_, float* __restrict__ out) {
    const int K = CC;
    __shared__ uint32_t AsH[128][APAD];
    __shared__ uint32_t AsL[128][APAD];
    __shared__ uint32_t BsH[16][BPAD];
    __shared__ uint32_t BsL[16][BPAD];
    int tid = threadIdx.x;
    int m0 = blockIdx.y * 128, n0 = blockIdx.x * 128;
    int mat  = n0 >> 10;
    int rem0 = n0 & 1023;
    const float* W  = (mat == 0) ? Wq : (mat == 1) ? Wk : Wv;
    const float* bb = (mat == 0) ? bq : (mat == 1) ? bk_ : bv_;

    int lane = tid & 31, warp = tid >> 5;
    int wy = warp >> 2, wx = warp & 3;
    int lr = lane >> 2, lc = lane & 3;

    float acc[4][4][4];
    #pragma unroll
    for (int i = 0; i < 4; i++)
        #pragma unroll
        for (int j = 0; j < 4; j++)
            #pragma unroll
            for (int f = 0; f < 4; f++) acc[i][j][f] = 0.f;

    int ar = tid >> 2, ak4 = (tid & 3) * 4;
    int bkr = tid >> 5, bn4 = (tid & 31) * 4;
    const float* Ap0 = A + (size_t)(m0 + ar) * K + ak4;
    const float* Ap1 = A + (size_t)(m0 + ar + 64) * K + ak4;
    int nb = rem0 + bn4;
    int hh = nb >> 6, dd = nb & 63;
    const float* Wp = W + ((size_t)hh << 16) + (size_t)bkr * DHH + dd;

    for (int k0 = 0; k0 < K; k0 += 16) {
        float4 av0 = *(const float4*)(Ap0 + k0);
        float4 av1 = *(const float4*)(Ap1 + k0);
        float4 bv0 = *(const float4*)(Wp + (size_t)k0 * DHH);
        float4 bv1 = *(const float4*)(Wp + (size_t)(k0 + 8) * DHH);
        split_tf(av0.x, AsH[ar][ak4+0], AsL[ar][ak4+0]);
        split_tf(av0.y, AsH[ar][ak4+1], AsL[ar][ak4+1]);
        split_tf(av0.z, AsH[ar][ak4+2], AsL[ar][ak4+2]);
        split_tf(av0.w, AsH[ar][ak4+3], AsL[ar][ak4+3]);
        split_tf(av1.x, AsH[ar+64][ak4+0], AsL[ar+64][ak4+0]);
        split_tf(av1.y, AsH[ar+64][ak4+1], AsL[ar+64][ak4+1]);
        split_tf(av1.z, AsH[ar+64][ak4+2], AsL[ar+64][ak4+2]);
        split_tf(av1.w, AsH[ar+64][ak4+3], AsL[ar+64][ak4+3]);
        split_tf(bv0.x, BsH[bkr][bn4+0], BsL[bkr][bn4+0]);
        split_tf(bv0.y, BsH[bkr][bn4+1], BsL[bkr][bn4+1]);
        split_tf(bv0.z, BsH[bkr][bn4+2], BsL[bkr][bn4+2]);
        split_tf(bv0.w, BsH[bkr][bn4+3], BsL[bkr][bn4+3]);
        split_tf(bv1.x, BsH[bkr+8][bn4+0], BsL[bkr+8][bn4+0]);
        split_tf(bv1.y, BsH[bkr+8][bn4+1], BsL[bkr+8][bn4+1]);
        split_tf(bv1.z, BsH[bkr+8][bn4+2], BsL[bkr+8][bn4+2]);
        split_tf(bv1.w, BsH[bkr+8][bn4+3], BsL[bkr+8][bn4+3]);
        __syncthreads();
        #pragma unroll
        for (int ks = 0; ks < 2; ks++) {
            int kk = ks * 8 + lc;
            uint32_t afH[4][4], afL[4][4];
            #pragma unroll
            for (int mi = 0; mi < 4; mi++) {
                int mrow = wy*64 + mi*16 + lr;
                afH[mi][0] = AsH[mrow][kk];   afL[mi][0] = AsL[mrow][kk];
                afH[mi][1] = AsH[mrow+8][kk]; afL[mi][1] = AsL[mrow+8][kk];
                afH[mi][2] = AsH[mrow][kk+4];   afL[mi][2] = AsL[mrow][kk+4];
                afH[mi][3] = AsH[mrow+8][kk+4]; afL[mi][3] = AsL[mrow+8][kk+4];
            }
            #pragma unroll
            for (int nj = 0; nj < 4; nj++) {
                int nc = wx*32 + nj*8 + lr;
                uint32_t bfH[2], bfL[2];
                bfH[0] = BsH[ks*8 + lc][nc];     bfL[0] = BsL[ks*8 + lc][nc];
                bfH[1] = BsH[ks*8 + 4 + lc][nc]; bfL[1] = BsL[ks*8 + 4 + lc][nc];
                #pragma unroll
                for (int mi = 0; mi < 4; mi++) {
                    MMA_TF32(acc[mi][nj], afL[mi], bfH);
                    MMA_TF32(acc[mi][nj], afH[mi], bfL);
                    MMA_TF32(acc[mi][nj], afH[mi], bfH);
                }
            }
        }
        __syncthreads();
    }
    float* Co = out + ((size_t)mat << 23);
    #pragma unroll
    for (int mi = 0; mi < 4; mi++) {
        #pragma unroll
        for (int nj = 0; nj < 4; nj++) {
            int row = m0 + wy*64 + mi*16 + lr;
            int col = rem0 + wx*32 + nj*8 + 2*lc;
            float b0 = bb[col], b1 = bb[col+1];
            float2 v0 = make_float2(acc[mi][nj][0] + b0, acc[mi][nj][1] + b1);
            float2 v1 = make_float2(acc[mi][nj][2] + b0, acc[mi][nj][3] + b1);
            *(float2*)(Co + (size_t)row * CC + col) = v0;
            *(float2*)(Co + (size_t)(row+8) * CC + col) = v1;
        }
    }
}

// ================= flash attention (fp32) =================
#define APITCH 68
__global__ void attn_kernel(const float* __restrict__ Q, const float* __restrict__ Km,
                            const float* __restrict__ V, float* __restrict__ O) {
    extern __shared__ float smem[];
    float (*Qs)[APITCH] = (float(*)[APITCH])(smem);
    float (*Ks)[APITCH] = (float(*)[APITCH])(smem + 64*APITCH);
    float (*Vs)[APITCH] = (float(*)[APITCH])(smem + 2*64*APITCH);
    float (*Ps)[APITCH] = (float(*)[APITCH])(smem + 3*64*APITCH);

    int r0 = blockIdx.x * 64;
    int h  = blockIdx.y;
    int b  = blockIdx.z;
    size_t base = (size_t)b * TT * CC + h * DHH;
    int tid = threadIdx.x, ty = tid >> 4, tx = tid & 15;

    {
        int lr = tid >> 4, c4 = (tid & 15) * 4;
        #pragma unroll
        for (int p = 0; p < 4; p++) {
            int row = p * 16 + lr;
            *(float4*)&Qs[row][c4] =
                *(const float4*)(Q + base + (size_t)(r0 + row) * CC + c4);
        }
    }
    float acc[4][4];
    #pragma unroll
    for (int i = 0; i < 4; i++)
        #pragma unroll
        for (int j = 0; j < 4; j++) acc[i][j] = 0.f;
    float mrow[4] = {-3e38f, -3e38f, -3e38f, -3e38f};
    float lrow[4] = {0.f, 0.f, 0.f, 0.f};

    for (int s0 = 0; s0 < TT; s0 += 64) {
        __syncthreads();
        {
            int lr = tid >> 4, c4 = (tid & 15) * 4;
            #pragma unroll
            for (int p = 0; p < 4; p++) {
                int row = p * 16 + lr;
                size_t g = base + (size_t)(s0 + row) * CC + c4;
                *(float4*)&Ks[row][c4] = *(const float4*)(Km + g);
                *(float4*)&Vs[row][c4] = *(const float4*)(V + g);
            }
        }
        __syncthreads();

        float sv[4][4];
        #pragma unroll
        for (int i = 0; i < 4; i++)
            #pragma unroll
            for (int j = 0; j < 4; j++) sv[i][j] = 0.f;
        #pragma unroll
        for (int d4 = 0; d4 < 16; d4++) {
            float4 qr[4], kr[4];
            #pragma unroll
            for (int i = 0; i < 4; i++) qr[i] = *(const float4*)&Qs[ty*4 + i][d4*4];
            #pragma unroll
            for (int j = 0; j < 4; j++) kr[j] = *(const float4*)&Ks[tx + 16*j][d4*4];
            #pragma unroll
            for (int i = 0; i < 4; i++)
                #pragma unroll
                for (int j = 0; j < 4; j++) {
                    sv[i][j] = fmaf(qr[i].x, kr[j].x, sv[i][j]);
                    sv[i][j] = fmaf(qr[i].y, kr[j].y, sv[i][j]);
                    sv[i][j] = fmaf(qr[i].z, kr[j].z, sv[i][j]);
                    sv[i][j] = fmaf(qr[i].w, kr[j].w, sv[i][j]);
                }
        }
        #pragma unroll
        for (int i = 0; i < 4; i++) {
            #pragma unroll
            for (int j = 0; j < 4; j++) sv[i][j] *= 8.0f;
            float mt = fmaxf(fmaxf(sv[i][0], sv[i][1]), fmaxf(sv[i][2], sv[i][3]));
            #pragma unroll
            for (int off = 8; off >= 1; off >>= 1)
                mt = fmaxf(mt, __shfl_xor_sync(0xffffffffu, mt, off, 16));
            float mnew  = fmaxf(mrow[i], mt);
            float alpha = __expf(mrow[i] - mnew);
            float psum  = 0.f;
            #pragma unroll
            for (int j = 0; j < 4; j++) {
                float p = __expf(sv[i][j] - mnew);
                Ps[ty*4 + i][tx + 16*j] = p;
                psum += p;
            }
            #pragma unroll
            for (int off = 8; off >= 1; off >>= 1)
                psum += __shfl_xor_sync(0xffffffffu, psum, off, 16);
            lrow[i] = lrow[i] * alpha + psum;
            mrow[i] = mnew;
            #pragma unroll
            for (int j = 0; j < 4; j++) acc[i][j] *= alpha;
        }
        __syncthreads();
        #pragma unroll 4
        for (int k = 0; k < 64; k++) {
            float pv[4], vv[4];
            #pragma unroll
            for (int i = 0; i < 4; i++) pv[i] = Ps[ty*4 + i][k];
            #pragma unroll
            for (int j = 0; j < 4; j++) vv[j] = Vs[k][tx + 16*j];
            #pragma unroll
            for (int i = 0; i < 4; i++)
                #pragma unroll
                for (int j = 0; j < 4; j++)
                    acc[i][j] = fmaf(pv[i], vv[j], acc[i][j]);
        }
    }
    #pragma unroll
    for (int i = 0; i < 4; i++) {
        float inv = 1.0f / lrow[i];
        #pragma unroll
        for (int j = 0; j < 4; j++)
            O[base + (size_t)(r0 + ty*4 + i) * CC + tx + 16*j] = acc[i][j] * inv;
    }
}

// ========================= launch =========================
extern "C" void kernel_launch(void* const* d_in, const int* in_sizes, int n_in,
                              void* d_out, int out_size) {
    const float* x     = (const float*)d_in[0];
    const float* Wq    = (const float*)d_in[1];
    const float* bq    = (const float*)d_in[2];
    const float* Wk    = (const float*)d_in[3];
    const float* bk    = (const float*)d_in[4];
    const float* Wv    = (const float*)d_in[5];
    const float* bv    = (const float*)d_in[6];
    const float* Wo    = (const float*)d_in[7];
    const float* bo    = (const float*)d_in[8];
    const float* ln1g  = (const float*)d_in[9];
    const float* ln1b  = (const float*)d_in[10];
    const float* ln2g  = (const float*)d_in[11];
    const float* ln2b  = (const float*)d_in[12];
    const float* W1    = (const float*)d_in[13];
    const float* b1    = (const float*)d_in[14];
    const float* W2    = (const float*)d_in[15];
    const float* b2    = (const float*)d_in[16];
    float* out = (float*)d_out;

    float *xn, *qkv, *o, *x1, *xn2, *ffn;
    cudaGetSymbolAddress((void**)&xn,  g_xn);
    cudaGetSymbolAddress((void**)&qkv, g_qkv);
    cudaGetSymbolAddress((void**)&o,   g_o);
    cudaGetSymbolAddress((void**)&x1,  g_x1);
    cudaGetSymbolAddress((void**)&xn2, g_xn2);
    cudaGetSymbolAddress((void**)&ffn, g_ffn);

    const int ATTN_SMEM = 4 * 64 * APITCH * sizeof(float);  // 69632 B
    cudaFuncSetAttribute(attn_kernel, cudaFuncAttributeMaxDynamicSharedMemorySize, ATTN_SMEM);

    // 1) LN1
    ln_kernel<<<MM, 256>>>(x, ln1g, ln1b, xn);
    // 2) QKV (3xTF32 tensor core)
    gemm_qkv_tc<<<dim3(24, 64), 256>>>(xn, Wq, Wk, Wv, bq, bk, bv, qkv);
    // 3) attention (fp32 SIMT)
    attn_kernel<<<dim3(TT/64, HH, BB), 256, ATTN_SMEM>>>(
        qkv, qkv + (1ull << 23), qkv + (2ull << 23), o);
    // 4) out proj + residual (tf32 TC)
    gemm_tc<false, true><<<dim3(8, 64), 256>>>(o, Wo, bo, x, x1, MM, CC, CC);
    // 5) LN2
    ln_kernel<<<MM, 256>>>(x1, ln2g, ln2b, xn2);
    // 6) FFN1 (relu, tf32 TC)
    gemm_tc<true, false><<<dim3(32, 64), 256>>>(xn2, W1, b1, nullptr, ffn, MM, DFF, CC);
    // 7) FFN2 + residual -> out (tf32 TC)
    gemm_tc<false, true><<<dim3(8, 64), 256>>>(ffn, W2, b2, x1, out, MM, CC, DFF);
}

// round 4
// speedup vs baseline: 2.4988x; 1.6090x over previous
#include <cuda_runtime.h>
#include <math.h>
#include <stdint.h>

#define BB 4
#define TT 2048
#define CC 1024
#define HH 16
#define DHH 64
#define DFF 4096
#define MM (BB*TT)   /* 8192 */

// -------- scratch (device globals; no allocation) --------
__device__ float g_xnh[(size_t)MM*CC];
__device__ float g_xnl[(size_t)MM*CC];
__device__ float g_qh [(size_t)MM*CC];
__device__ float g_ql [(size_t)MM*CC];
__device__ float g_kh [(size_t)MM*CC];
__device__ float g_kl [(size_t)MM*CC];
__device__ float g_v  [(size_t)MM*CC];
__device__ float g_o  [(size_t)MM*CC];
__device__ float g_x1 [(size_t)MM*CC];
__device__ float g_xn2[(size_t)MM*CC];
__device__ float g_ffn[(size_t)MM*DFF];
__device__ float g_wbh[(size_t)CC*3072];
__device__ float g_wbl[(size_t)CC*3072];
__device__ float g_wor[(size_t)CC*CC];
__device__ float g_w1r[(size_t)CC*DFF];
__device__ float g_w2r[(size_t)DFF*CC];

// ======================= helpers =======================
__device__ __forceinline__ uint32_t f2tf(float f) {
    uint32_t u;
    asm("cvt.rna.tf32.f32 %0, %1;" : "=r"(u) : "f"(f));
    return u;
}
__device__ __forceinline__ float f2tff(float f) { return __uint_as_float(f2tf(f)); }

#define MMA_TF32(d, a0,a1,a2,a3, b0,b1) \
    asm volatile("mma.sync.aligned.m16n8k8.row.col.f32.tf32.tf32.f32 " \
        "{%0,%1,%2,%3}, {%4,%5,%6,%7}, {%8,%9}, {%0,%1,%2,%3};" \
        : "+f"(d[0]), "+f"(d[1]), "+f"(d[2]), "+f"(d[3]) \
        : "r"(a0), "r"(a1), "r"(a2), "r"(a3), "r"(b0), "r"(b1))

__device__ __forceinline__ void cpa16(uint32_t dst, const void* src) {
    asm volatile("cp.async.ca.shared.global [%0], [%1], 16;\n" :: "r"(dst), "l"(src));
}
__device__ __forceinline__ void cpcommit() { asm volatile("cp.async.commit_group;\n" ::); }
template<int N> __device__ __forceinline__ void cpwait() {
    asm volatile("cp.async.wait_group %0;\n" :: "n"(N));
}

// ======================= prep kernels =======================
// Build Wb[k][n], n in [0,3072): mat=n>>10, h=(n>>6)&15, d=n&63
__global__ void prep_qkv_w(const float* __restrict__ Wq, const float* __restrict__ Wk,
                           const float* __restrict__ Wv,
                           float* __restrict__ bh, float* __restrict__ bl) {
    int idx = blockIdx.x * 256 + threadIdx.x;           // < 1024*3072
    int k = idx / 3072, n = idx - k * 3072;
    int mat = n >> 10, h = (n >> 6) & 15, d = n & 63;
    const float* W = (mat == 0) ? Wq : (mat == 1) ? Wk : Wv;
    float w = W[h * 65536 + k * 64 + d];
    float hi = f2tff(w);
    bh[idx] = hi;
    bl[idx] = f2tff(w - hi);
}

__global__ void prep_round(const float* __restrict__ W, float* __restrict__ out) {
    int idx = blockIdx.x * 256 + threadIdx.x;
    out[idx] = f2tff(W[idx]);
}

// ======================= LayerNorm =======================
template<bool SPLIT>
__global__ void ln_kernel(const float* __restrict__ X, const float* __restrict__ gam,
                          const float* __restrict__ bet,
                          float* __restrict__ Yh, float* __restrict__ Yl) {
    int row = blockIdx.x;
    const float* xr = X + (size_t)row * CC;
    int tid = threadIdx.x;
    float4 v = *(const float4*)(xr + tid * 4);
    float s  = v.x + v.y + v.z + v.w;
    float ss = v.x*v.x + v.y*v.y + v.z*v.z + v.w*v.w;
    #pragma unroll
    for (int off = 16; off >= 1; off >>= 1) {
        s  += __shfl_xor_sync(0xffffffffu, s,  off);
        ss += __shfl_xor_sync(0xffffffffu, ss, off);
    }
    __shared__ float sb[8], ssb[8];
    if ((tid & 31) == 0) { sb[tid >> 5] = s; ssb[tid >> 5] = ss; }
    __syncthreads();
    s = 0.f; ss = 0.f;
    #pragma unroll
    for (int w = 0; w < 8; w++) { s += sb[w]; ss += ssb[w]; }
    float mu  = s * (1.0f / CC);
    float var = ss * (1.0f / CC) - mu * mu;
    float rs  = rsqrtf(var + 1e-5f);
    float4 gv = *(const float4*)(gam + tid * 4);
    float4 bv = *(const float4*)(bet + tid * 4);
    float y[4];
    y[0] = (v.x - mu) * rs * gv.x + bv.x;
    y[1] = (v.y - mu) * rs * gv.y + bv.y;
    y[2] = (v.z - mu) * rs * gv.z + bv.z;
    y[3] = (v.w - mu) * rs * gv.w + bv.w;
    float4 oh, ol;
    float* ph = (float*)&oh; float* pl = (float*)&ol;
    #pragma unroll
    for (int i = 0; i < 4; i++) {
        float hi = f2tff(y[i]);
        ph[i] = hi;
        if (SPLIT) pl[i] = f2tff(y[i] - hi);
    }
    *(float4*)(Yh + (size_t)row * CC + tid * 4) = oh;
    if (SPLIT) *(float4*)(Yl + (size_t)row * CC + tid * 4) = ol;
}

// ============ double-buffered tf32 GEMM (pre-rounded inputs) ============
// A[M,K], B[K,N] row-major, both already tf32-rounded floats.
#define APITCHG 20
#define BPITCHG 136
template<bool RELU, bool RESID, bool ROUND>
__global__ __launch_bounds__(256) void gemm_db(
        const float* __restrict__ A, const float* __restrict__ B,
        const float* __restrict__ bias, const float* __restrict__ resid,
        float* __restrict__ C, int M, int N, int K) {
    __shared__ float As[2][128][APITCHG];
    __shared__ float Bs[2][16][BPITCHG];
    int tid = threadIdx.x;
    int m0 = blockIdx.y * 128, n0 = blockIdx.x * 128;
    int lane = tid & 31, warp = tid >> 5;
    int wy = warp >> 2, wx = warp & 3;
    int lr = lane >> 2, lc = lane & 3;

    float acc[4][4][4];
    #pragma unroll
    for (int i = 0; i < 4; i++)
        #pragma unroll
        for (int j = 0; j < 4; j++)
            #pragma unroll
            for (int f = 0; f < 4; f++) acc[i][j][f] = 0.f;

    // loader mapping
    int am0 = tid >> 2,  ak0 = (tid & 3);        // chunk c=tid: m=c>>2, k4=c&3 ; +256 -> m+64
    int bk0 = tid >> 5,  bn0 = (tid & 31);       // chunk c=tid: k=c>>5, n4=c&31; +256 -> k+8

    uint32_t sA = (uint32_t)__cvta_generic_to_shared(&As[0][0][0]);
    uint32_t sB = (uint32_t)__cvta_generic_to_shared(&Bs[0][0][0]);
    const int A_ST = 128 * APITCHG * 4;  // stage stride bytes
    const int B_ST = 16 * BPITCHG * 4;

    int NT = K >> 4;
    // prefetch stage 0
    {
        int k0 = 0;
        cpa16(sA + (am0*APITCHG + ak0*4)*4,        A + (size_t)(m0+am0)*K + k0 + ak0*4);
        cpa16(sA + ((am0+64)*APITCHG + ak0*4)*4,   A + (size_t)(m0+am0+64)*K + k0 + ak0*4);
        cpa16(sB + (bk0*BPITCHG + bn0*4)*4,        B + (size_t)(k0+bk0)*N + n0 + bn0*4);
        cpa16(sB + ((bk0+8)*BPITCHG + bn0*4)*4,    B + (size_t)(k0+bk0+8)*N + n0 + bn0*4);
        cpcommit();
    }
    for (int kt = 0; kt < NT; kt++) {
        int cur = kt & 1;
        if (kt + 1 < NT) {
            int nx = (kt + 1) & 1, k0 = (kt + 1) << 4;
            cpa16(sA + nx*A_ST + (am0*APITCHG + ak0*4)*4,      A + (size_t)(m0+am0)*K + k0 + ak0*4);
            cpa16(sA + nx*A_ST + ((am0+64)*APITCHG + ak0*4)*4, A + (size_t)(m0+am0+64)*K + k0 + ak0*4);
            cpa16(sB + nx*B_ST + (bk0*BPITCHG + bn0*4)*4,      B + (size_t)(k0+bk0)*N + n0 + bn0*4);
            cpa16(sB + nx*B_ST + ((bk0+8)*BPITCHG + bn0*4)*4,  B + (size_t)(k0+bk0+8)*N + n0 + bn0*4);
            cpcommit();
            cpwait<1>();
        } else {
            cpwait<0>();
        }
        __syncthreads();
        #pragma unroll
        for (int ks = 0; ks < 2; ks++) {
            int kk = ks * 8 + lc;
            uint32_t af[4][4], bf[4][2];
            #pragma unroll
            for (int mi = 0; mi < 4; mi++) {
                int mrow = wy*64 + mi*16 + lr;
                af[mi][0] = __float_as_uint(As[cur][mrow][kk]);
                af[mi][1] = __float_as_uint(As[cur][mrow+8][kk]);
                af[mi][2] = __float_as_uint(As[cur][mrow][kk+4]);
                af[mi][3] = __float_as_uint(As[cur][mrow+8][kk+4]);
            }
            #pragma unroll
            for (int nj = 0; nj < 4; nj++) {
                int nc = wx*32 + nj*8 + lr;
                bf[nj][0] = __float_as_uint(Bs[cur][ks*8 + lc][nc]);
                bf[nj][1] = __float_as_uint(Bs[cur][ks*8 + 4 + lc][nc]);
            }
            #pragma unroll
            for (int mi = 0; mi < 4; mi++)
                #pragma unroll
                for (int nj = 0; nj < 4; nj++)
                    MMA_TF32(acc[mi][nj], af[mi][0],af[mi][1],af[mi][2],af[mi][3],
                             bf[nj][0],bf[nj][1]);
        }
        __syncthreads();
    }
    #pragma unroll
    for (int mi = 0; mi < 4; mi++) {
        #pragma unroll
        for (int nj = 0; nj < 4; nj++) {
            int row = m0 + wy*64 + mi*16 + lr;
            int col = n0 + wx*32 + nj*8 + 2*lc;
            float b0 = bias[col], b1 = bias[col+1];
            float2 v0 = make_float2(acc[mi][nj][0] + b0, acc[mi][nj][1] + b1);
            float2 v1 = make_float2(acc[mi][nj][2] + b0, acc[mi][nj][3] + b1);
            if (RESID) {
                float2 r0 = *(const float2*)(resid + (size_t)row * N + col);
                float2 r1 = *(const float2*)(resid + (size_t)(row+8) * N + col);
                v0.x += r0.x; v0.y += r0.y; v1.x += r1.x; v1.y += r1.y;
            }
            if (RELU) {
                v0.x = fmaxf(v0.x, 0.f); v0.y = fmaxf(v0.y, 0.f);
                v1.x = fmaxf(v1.x, 0.f); v1.y = fmaxf(v1.y, 0.f);
            }
            if (ROUND) {
                v0.x = f2tff(v0.x); v0.y = f2tff(v0.y);
                v1.x = f2tff(v1.x); v1.y = f2tff(v1.y);
            }
            *(float2*)(C + (size_t)row * N + col) = v0;
            *(float2*)(C + (size_t)(row+8) * N + col) = v1;
        }
    }
}

// ============ QKV GEMM: 3xTF32 for Q,K; 1x for V; split epilogue ============
// A hi/lo = xn split [8192][1024]; B hi/lo = prepped [1024][3072].
__global__ __launch_bounds__(256) void gemm_qkv_db(
        const float* __restrict__ Ah_, const float* __restrict__ Al_,
        const float* __restrict__ Bh_, const float* __restrict__ Bl_,
        const float* __restrict__ bq, const float* __restrict__ bk_,
        const float* __restrict__ bv_,
        float* __restrict__ qh, float* __restrict__ ql,
        float* __restrict__ kh, float* __restrict__ kl,
        float* __restrict__ vv) {
    extern __shared__ float sm[];
    // layout (floats): Ah[2][128][20] @0 (5120), Al @5120, Bh[2][16][136] @10240 (4352), Bl @14592
    float* Ah = sm;           float* Al = sm + 5120;
    float* Bh = sm + 10240;   float* Bl = sm + 14592;
    const int K = CC, N = 3072;
    int tid = threadIdx.x;
    int m0 = blockIdx.y * 128, n0 = blockIdx.x * 128;
    int mat = n0 >> 10;
    int rem0 = n0 & 1023;
    bool three = (mat < 2);

    int lane = tid & 31, warp = tid >> 5;
    int wy = warp >> 2, wx = warp & 3;
    int lr = lane >> 2, lc = lane & 3;

    float acc[4][4][4];
    #pragma unroll
    for (int i = 0; i < 4; i++)
        #pragma unroll
        for (int j = 0; j < 4; j++)
            #pragma unroll
            for (int f = 0; f < 4; f++) acc[i][j][f] = 0.f;

    int am0 = tid >> 2, ak0 = (tid & 3);
    int bk0 = tid >> 5, bn0 = (tid & 31);
    uint32_t sAh = (uint32_t)__cvta_generic_to_shared(Ah);
    uint32_t sAl = (uint32_t)__cvta_generic_to_shared(Al);
    uint32_t sBh = (uint32_t)__cvta_generic_to_shared(Bh);
    uint32_t sBl = (uint32_t)__cvta_generic_to_shared(Bl);
    const int A_ST = 128 * APITCHG * 4;
    const int B_ST = 16 * BPITCHG * 4;
    const int NT = K >> 4;

    // prefetch
    auto pf = [&](int kt, int st) {
        int k0 = kt << 4;
        uint32_t aoff = (am0*APITCHG + ak0*4)*4 + st*A_ST;
        uint32_t aoff2 = ((am0+64)*APITCHG + ak0*4)*4 + st*A_ST;
        uint32_t boff = (bk0*BPITCHG + bn0*4)*4 + st*B_ST;
        uint32_t boff2 = ((bk0+8)*BPITCHG + bn0*4)*4 + st*B_ST;
        const float* a0 = Ah_ + (size_t)(m0+am0)*K + k0 + ak0*4;
        const float* a1 = Ah_ + (size_t)(m0+am0+64)*K + k0 + ak0*4;
        const float* b0 = Bh_ + (size_t)(k0+bk0)*N + n0 + bn0*4;
        const float* b1 = Bh_ + (size_t)(k0+bk0+8)*N + n0 + bn0*4;
        cpa16(sAh + aoff, a0); cpa16(sAh + aoff2, a1);
        cpa16(sBh + boff, b0); cpa16(sBh + boff2, b1);
        if (three) {
            cpa16(sAl + aoff,  Al_ + (size_t)(m0+am0)*K + k0 + ak0*4);
            cpa16(sAl + aoff2, Al_ + (size_t)(m0+am0+64)*K + k0 + ak0*4);
            cpa16(sBl + boff,  Bl_ + (size_t)(k0+bk0)*N + n0 + bn0*4);
            cpa16(sBl + boff2, Bl_ + (size_t)(k0+bk0+8)*N + n0 + bn0*4);
        }
    };
    pf(0, 0); cpcommit();
    for (int kt = 0; kt < NT; kt++) {
        int cur = kt & 1;
        if (kt + 1 < NT) { pf(kt+1, (kt+1)&1); cpcommit(); cpwait<1>(); }
        else cpwait<0>();
        __syncthreads();
        #pragma unroll
        for (int ks = 0; ks < 2; ks++) {
            int kk = ks * 8 + lc;
            uint32_t afh[4][4], afl[4][4], bfh[4][2], bfl[4][2];
            #pragma unroll
            for (int mi = 0; mi < 4; mi++) {
                int mrow = wy*64 + mi*16 + lr;
                int o1 = cur*2560 + mrow*APITCHG;
                int o2 = cur*2560 + (mrow+8)*APITCHG;
                afh[mi][0] = __float_as_uint(Ah[o1 + kk]);
                afh[mi][1] = __float_as_uint(Ah[o2 + kk]);
                afh[mi][2] = __float_as_uint(Ah[o1 + kk + 4]);
                afh[mi][3] = __float_as_uint(Ah[o2 + kk + 4]);
                if (three) {
                    afl[mi][0] = __float_as_uint(Al[o1 + kk]);
                    afl[mi][1] = __float_as_uint(Al[o2 + kk]);
                    afl[mi][2] = __float_as_uint(Al[o1 + kk + 4]);
                    afl[mi][3] = __float_as_uint(Al[o2 + kk + 4]);
                }
            }
            #pragma unroll
            for (int nj = 0; nj < 4; nj++) {
                int nc = wx*32 + nj*8 + lr;
                int o1 = cur*2176 + (ks*8+lc)*BPITCHG + nc;
                int o2 = cur*2176 + (ks*8+4+lc)*BPITCHG + nc;
                bfh[nj][0] = __float_as_uint(Bh[o1]);
                bfh[nj][1] = __float_as_uint(Bh[o2]);
                if (three) {
                    bfl[nj][0] = __float_as_uint(Bl[o1]);
                    bfl[nj][1] = __float_as_uint(Bl[o2]);
                }
            }
            #pragma unroll
            for (int mi = 0; mi < 4; mi++)
                #pragma unroll
                for (int nj = 0; nj < 4; nj++) {
                    if (three) {
                        MMA_TF32(acc[mi][nj], afl[mi][0],afl[mi][1],afl[mi][2],afl[mi][3],
                                 bfh[nj][0],bfh[nj][1]);
                        MMA_TF32(acc[mi][nj], afh[mi][0],afh[mi][1],afh[mi][2],afh[mi][3],
                                 bfl[nj][0],bfl[nj][1]);
                    }
                    MMA_TF32(acc[mi][nj], afh[mi][0],afh[mi][1],afh[mi][2],afh[mi][3],
                             bfh[nj][0],bfh[nj][1]);
                }
        }
        __syncthreads();
    }
    const float* bias = (mat == 0) ? bq : (mat == 1) ? bk_ : bv_;
    #pragma unroll
    for (int mi = 0; mi < 4; mi++) {
        #pragma unroll
        for (int nj = 0; nj < 4; nj++) {
            int row = m0 + wy*64 + mi*16 + lr;
            int col = rem0 + wx*32 + nj*8 + 2*lc;
            float b0 = bias[col], b1 = bias[col+1];
            float x0 = acc[mi][nj][0] + b0, x1v = acc[mi][nj][1] + b1;
            float x2 = acc[mi][nj][2] + b0, x3 = acc[mi][nj][3] + b1;
            size_t i0 = (size_t)row * CC + col, i1 = (size_t)(row+8) * CC + col;
            if (mat == 2) {
                *(float2*)(vv + i0) = make_float2(f2tff(x0), f2tff(x1v));
                *(float2*)(vv + i1) = make_float2(f2tff(x2), f2tff(x3));
            } else {
                float* oh = (mat == 0) ? qh : kh;
                float* ol = (mat == 0) ? ql : kl;
                float h0 = f2tff(x0), h1 = f2tff(x1v), h2 = f2tff(x2), h3 = f2tff(x3);
                *(float2*)(oh + i0) = make_float2(h0, h1);
                *(float2*)(oh + i1) = make_float2(h2, h3);
                *(float2*)(ol + i0) = make_float2(f2tff(x0-h0), f2tff(x1v-h1));
                *(float2*)(ol + i1) = make_float2(f2tff(x2-h2), f2tff(x3-h3));
            }
        }
    }
}

// ================= tensor-core flash attention =================
// BR=128, BC=64, DH=64, 8 warps; warp w owns rows 16w..16w+15.
// QK^T in 3xTF32 (Q,K pre-split), PV in 1x tf32. Scale *8 folded into Q.
// smem floats: Ph[128][68] @0, Kh[2][64][68] @8704, Kl @17408, Vs[2][64][72] @26112
#define ATSM (35328*4)
__global__ __launch_bounds__(256, 1) void attn_tc(
        const float* __restrict__ Qh_, const float* __restrict__ Ql_,
        const float* __restrict__ Kh_, const float* __restrict__ Kl_,
        const float* __restrict__ V_, float* __restrict__ O_) {
    extern __shared__ float sm[];
    float* Ph = sm;
    float* Kh = sm + 8704;
    float* Kl = sm + 17408;
    float* Vs = sm + 26112;
    uint32_t sKh = (uint32_t)__cvta_generic_to_shared(Kh);
    uint32_t sKl = (uint32_t)__cvta_generic_to_shared(Kl);
    uint32_t sVs = (uint32_t)__cvta_generic_to_shared(Vs);

    int tid = threadIdx.x;
    int lane = tid & 31, warp = tid >> 5;
    int lr = lane >> 2, lc = lane & 3;
    int r0 = blockIdx.x * 128;
    int h  = blockIdx.y;
    int b  = blockIdx.z;
    size_t base = (size_t)b * TT * CC + h * DHH;

    // K/V prefetch helper: tile t (64 rows), stage st
    int cs = tid >> 4, cd = (tid & 15);   // chunk: s = cs + 16*i, d4 = cd
    auto pfkv = [&](int t, int st) {
        int s0 = t * 64;
        #pragma unroll
        for (int i = 0; i < 4; i++) {
            int s = cs + 16 * i;
            const float* gk = Kh_ + base + (size_t)(s0 + s) * CC + cd * 4;
            const float* gl = Kl_ + base + (size_t)(s0 + s) * CC + cd * 4;
            const float* gv = V_  + base + (size_t)(s0 + s) * CC + cd * 4;
            cpa16(sKh + (st*4352 + s*68 + cd*4)*4, gk);
            cpa16(sKl + (st*4352 + s*68 + cd*4)*4, gl);
            cpa16(sVs + (st*4608 + s*72 + cd*4)*4, gv);
        }
    };
    pfkv(0, 0); cpcommit();

    // ---- stage Q hi then lo through Ph, load frags (scaled by 8) ----
    uint32_t qfh[8][4], qfl[8][4];
    #pragma unroll
    for (int pass = 0; pass < 2; pass++) {
        const float* src = pass ? Ql_ : Qh_;
        #pragma unroll
        for (int i = 0; i < 8; i++) {
            int idx = tid + 256 * i;         // < 2048
            int row = idx >> 4, d4 = idx & 15;
            float4 q = *(const float4*)(src + base + (size_t)(r0 + row) * CC + d4 * 4);
            q.x *= 8.f; q.y *= 8.f; q.z *= 8.f; q.w *= 8.f;
            *(float4*)&Ph[row * 68 + d4 * 4] = q;
        }
        __syncthreads();
        #pragma unroll
        for (int kt = 0; kt < 8; kt++) {
            int o1 = (16*warp + lr) * 68 + kt*8 + lc;
            int o2 = (16*warp + 8 + lr) * 68 + kt*8 + lc;
            uint32_t f0 = __float_as_uint(Ph[o1]);
            uint32_t f1 = __float_as_uint(Ph[o2]);
            uint32_t f2 = __float_as_uint(Ph[o1 + 4]);
            uint32_t f3 = __float_as_uint(Ph[o2 + 4]);
            if (pass) { qfl[kt][0]=f0; qfl[kt][1]=f1; qfl[kt][2]=f2; qfl[kt][3]=f3; }
            else      { qfh[kt][0]=f0; qfh[kt][1]=f1; qfh[kt][2]=f2; qfh[kt][3]=f3; }
        }
        __syncthreads();
    }

    float oacc[8][4];
    #pragma unroll
    for (int dj = 0; dj < 8; dj++)
        #pragma unroll
        for (int f = 0; f < 4; f++) oacc[dj][f] = 0.f;
    float m0 = -3e38f, m1 = -3e38f, l0 = 0.f, l1 = 0.f;

    const int NTL = TT / 64;  // 32
    for (int t = 0; t < NTL; t++) {
        int st = t & 1;
        if (t + 1 < NTL) { pfkv(t+1, (t+1)&1); cpcommit(); cpwait<1>(); }
        else cpwait<0>();
        __syncthreads();

        // ---- S = (8Q) K^T, 3-term ----
        float s[8][4];
        #pragma unroll
        for (int nj = 0; nj < 8; nj++)
            #pragma unroll
            for (int f = 0; f < 4; f++) s[nj][f] = 0.f;
        #pragma unroll
        for (int kt = 0; kt < 8; kt++) {
            #pragma unroll
            for (int nj = 0; nj < 8; nj++) {
                int o1 = st*4352 + (nj*8 + lr)*68 + kt*8 + lc;
                uint32_t bh0 = __float_as_uint(Kh[o1]);
                uint32_t bh1 = __float_as_uint(Kh[o1 + 4]);
                uint32_t bl0 = __float_as_uint(Kl[o1]);
                uint32_t bl1 = __float_as_uint(Kl[o1 + 4]);
                MMA_TF32(s[nj], qfl[kt][0],qfl[kt][1],qfl[kt][2],qfl[kt][3], bh0, bh1);
                MMA_TF32(s[nj], qfh[kt][0],qfh[kt][1],qfh[kt][2],qfh[kt][3], bl0, bl1);
                MMA_TF32(s[nj], qfh[kt][0],qfh[kt][1],qfh[kt][2],qfh[kt][3], bh0, bh1);
            }
        }
        // ---- online softmax ----
        float mt0 = -3e38f, mt1 = -3e38f;
        #pragma unroll
        for (int nj = 0; nj < 8; nj++) {
            mt0 = fmaxf(mt0, fmaxf(s[nj][0], s[nj][1]));
            mt1 = fmaxf(mt1, fmaxf(s[nj][2], s[nj][3]));
        }
        mt0 = fmaxf(mt0, __shfl_xor_sync(0xffffffffu, mt0, 1));
        mt0 = fmaxf(mt0, __shfl_xor_sync(0xffffffffu, mt0, 2));
        mt1 = fmaxf(mt1, __shfl_xor_sync(0xffffffffu, mt1, 1));
        mt1 = fmaxf(mt1, __shfl_xor_sync(0xffffffffu, mt1, 2));
        float mn0 = fmaxf(m0, mt0), mn1 = fmaxf(m1, mt1);
        float al0 = __expf(m0 - mn0), al1 = __expf(m1 - mn1);
        float ps0 = 0.f, ps1 = 0.f;
        int pr0 = (16*warp + lr) * 68, pr1 = (16*warp + 8 + lr) * 68;
        #pragma unroll
        for (int nj = 0; nj < 8; nj++) {
            float p0 = __expf(s[nj][0] - mn0);
            float p1 = __expf(s[nj][1] - mn0);
            float p2 = __expf(s[nj][2] - mn1);
            float p3 = __expf(s[nj][3] - mn1);
            ps0 += p0 + p1; ps1 += p2 + p3;
            *(float2*)&Ph[pr0 + nj*8 + 2*lc] = make_float2(f2tff(p0), f2tff(p1));
            *(float2*)&Ph[pr1 + nj*8 + 2*lc] = make_float2(f2tff(p2), f2tff(p3));
        }
        ps0 += __shfl_xor_sync(0xffffffffu, ps0, 1);
        ps0 += __shfl_xor_sync(0xffffffffu, ps0, 2);
        ps1 += __shfl_xor_sync(0xffffffffu, ps1, 1);
        ps1 += __shfl_xor_sync(0xffffffffu, ps1, 2);
        l0 = l0 * al0 + ps0;
        l1 = l1 * al1 + ps1;
        m0 = mn0; m1 = mn1;
        #pragma unroll
        for (int dj = 0; dj < 8; dj++) {
            oacc[dj][0] *= al0; oacc[dj][1] *= al0;
            oacc[dj][2] *= al1; oacc[dj][3] *= al1;
        }
        __syncwarp();
        // ---- O += P V ----
        #pragma unroll
        for (int ks = 0; ks < 8; ks++) {
            uint32_t a0 = __float_as_uint(Ph[pr0 + ks*8 + lc]);
            uint32_t a1 = __float_as_uint(Ph[pr1 + ks*8 + lc]);
            uint32_t a2 = __float_as_uint(Ph[pr0 + ks*8 + lc + 4]);
            uint32_t a3 = __float_as_uint(Ph[pr1 + ks*8 + lc + 4]);
            #pragma unroll
            for (int dj = 0; dj < 8; dj++) {
                int o1 = st*4608 + (ks*8 + lc)*72 + dj*8 + lr;
                int o2 = st*4608 + (ks*8 + 4 + lc)*72 + dj*8 + lr;
                uint32_t b0 = __float_as_uint(Vs[o1]);
                uint32_t b1 = __float_as_uint(Vs[o2]);
                MMA_TF32(oacc[dj], a0, a1, a2, a3, b0, b1);
            }
        }
        __syncthreads();
    }
    // ---- epilogue: O / l, round to tf32 (feeds Wo GEMM) ----
    float inv0 = 1.f / l0, inv1 = 1.f / l1;
    int row0 = r0 + 16*warp + lr, row1 = row0 + 8;
    #pragma unroll
    for (int dj = 0; dj < 8; dj++) {
        int col = dj*8 + 2*lc;
        *(float2*)(O_ + base + (size_t)row0 * CC + col) =
            make_float2(f2tff(oacc[dj][0]*inv0), f2tff(oacc[dj][1]*inv0));
        *(float2*)(O_ + base + (size_t)row1 * CC + col) =
            make_float2(f2tff(oacc[dj][2]*inv1), f2tff(oacc[dj][3]*inv1));
    }
}

// ========================= launch =========================
extern "C" void kernel_launch(void* const* d_in, const int* in_sizes, int n_in,
                              void* d_out, int out_size) {
    const float* x     = (const float*)d_in[0];
    const float* Wq    = (const float*)d_in[1];
    const float* bq    = (const float*)d_in[2];
    const float* Wk    = (const float*)d_in[3];
    const float* bk    = (const float*)d_in[4];
    const float* Wv    = (const float*)d_in[5];
    const float* bv    = (const float*)d_in[6];
    const float* Wo    = (const float*)d_in[7];
    const float* bo    = (const float*)d_in[8];
    const float* ln1g  = (const float*)d_in[9];
    const float* ln1b  = (const float*)d_in[10];
    const float* ln2g  = (const float*)d_in[11];
    const float* ln2b  = (const float*)d_in[12];
    const float* W1    = (const float*)d_in[13];
    const float* b1    = (const float*)d_in[14];
    const float* W2    = (const float*)d_in[15];
    const float* b2    = (const float*)d_in[16];
    float* out = (float*)d_out;

    float *xnh,*xnl,*qh,*ql,*kh,*kl,*vv,*o,*x1,*xn2,*ffn,*wbh,*wbl,*wor,*w1r,*w2r;
    cudaGetSymbolAddress((void**)&xnh, g_xnh);
    cudaGetSymbolAddress((void**)&xnl, g_xnl);
    cudaGetSymbolAddress((void**)&qh,  g_qh);
    cudaGetSymbolAddress((void**)&ql,  g_ql);
    cudaGetSymbolAddress((void**)&kh,  g_kh);
    cudaGetSymbolAddress((void**)&kl,  g_kl);
    cudaGetSymbolAddress((void**)&vv,  g_v);
    cudaGetSymbolAddress((void**)&o,   g_o);
    cudaGetSymbolAddress((void**)&x1,  g_x1);
    cudaGetSymbolAddress((void**)&xn2, g_xn2);
    cudaGetSymbolAddress((void**)&ffn, g_ffn);
    cudaGetSymbolAddress((void**)&wbh, g_wbh);
    cudaGetSymbolAddress((void**)&wbl, g_wbl);
    cudaGetSymbolAddress((void**)&wor, g_wor);
    cudaGetSymbolAddress((void**)&w1r, g_w1r);
    cudaGetSymbolAddress((void**)&w2r, g_w2r);

    const int QKV_SMEM = 18944 * 4;
    cudaFuncSetAttribute(gemm_qkv_db, cudaFuncAttributeMaxDynamicSharedMemorySize, QKV_SMEM);
    cudaFuncSetAttribute(attn_tc, cudaFuncAttributeMaxDynamicSharedMemorySize, ATSM);

    // weight prep (deterministic every call)
    prep_qkv_w<<<(CC*3072)/256, 256>>>(Wq, Wk, Wv, wbh, wbl);
    prep_round<<<(CC*CC)/256, 256>>>(Wo, wor);
    prep_round<<<(CC*DFF)/256, 256>>>(W1, w1r);
    prep_round<<<(DFF*CC)/256, 256>>>(W2, w2r);

    // 1) LN1 (split)
    ln_kernel<true><<<MM, 256>>>(x, ln1g, ln1b, xnh, xnl);
    // 2) QKV
    gemm_qkv_db<<<dim3(24, 64), 256, QKV_SMEM>>>(xnh, xnl, wbh, wbl,
                                                 bq, bk, bv, qh, ql, kh, kl, vv);
    // 3) attention
    attn_tc<<<dim3(TT/128, HH, BB), 256, ATSM>>>(qh, ql, kh, kl, vv, o);
    // 4) out proj + residual (raw x1)
    gemm_db<false, true, false><<<dim3(8, 64), 256>>>(o, wor, bo, x, x1, MM, CC, CC);
    // 5) LN2 (rounded)
    ln_kernel<false><<<MM, 256>>>(x1, ln2g, ln2b, xn2, nullptr);
    // 6) FFN1 (relu, rounded out)
    gemm_db<true, false, true><<<dim3(32, 64), 256>>>(xn2, w1r, b1, nullptr, ffn, MM, DFF, CC);
    // 7) FFN2 + residual -> out
    gemm_db<false, true, false><<<dim3(8, 64), 256>>>(ffn, w2r, b2, x1, out, MM, CC, DFF);
}

// round 5
// speedup vs baseline: 4.5941x; 1.8385x over previous
#include <cuda_runtime.h>
#include <cuda_fp16.h>
#include <math.h>
#include <stdint.h>

#define BB 4
#define TT 2048
#define CC 1024
#define HH 16
#define DHH 64
#define DFF 4096
#define MM (BB*TT)   /* 8192 */

// -------- scratch (device globals; no allocation) --------
__device__ __half g_xnh[(size_t)MM*CC];
__device__ __half g_xnl[(size_t)MM*CC];
__device__ __half g_qhh[(size_t)MM*CC];
__device__ __half g_qll[(size_t)MM*CC];
__device__ __half g_khh[(size_t)MM*CC];
__device__ __half g_kll[(size_t)MM*CC];
__device__ __half g_vhh[(size_t)MM*CC];
__device__ __half g_ohh[(size_t)MM*CC];
__device__ __half g_x2h[(size_t)MM*CC];
__device__ __half g_ffh[(size_t)MM*DFF];
__device__ float  g_x1 [(size_t)MM*CC];
__device__ __half g_wqh[(size_t)CC*3072];
__device__ __half g_wql[(size_t)CC*3072];
__device__ __half g_wot[(size_t)CC*CC];
__device__ __half g_w1t[(size_t)CC*DFF];
__device__ __half g_w2t[(size_t)DFF*CC];

// ======================= helpers =======================
__device__ __forceinline__ uint32_t smem_u32(const void* p) {
    return (uint32_t)__cvta_generic_to_shared(p);
}
#define LDM_X4(r0,r1,r2,r3, addr) \
    asm volatile("ldmatrix.sync.aligned.m8n8.x4.shared.b16 {%0,%1,%2,%3},[%4];" \
        : "=r"(r0),"=r"(r1),"=r"(r2),"=r"(r3) : "r"(addr))
#define LDM_X4T(r0,r1,r2,r3, addr) \
    asm volatile("ldmatrix.sync.aligned.m8n8.x4.trans.shared.b16 {%0,%1,%2,%3},[%4];" \
        : "=r"(r0),"=r"(r1),"=r"(r2),"=r"(r3) : "r"(addr))
#define MMA_F16(d, a0,a1,a2,a3, b0,b1) \
    asm volatile("mma.sync.aligned.m16n8k16.row.col.f32.f16.f16.f32 " \
        "{%0,%1,%2,%3},{%4,%5,%6,%7},{%8,%9},{%0,%1,%2,%3};" \
        : "+f"(d[0]),"+f"(d[1]),"+f"(d[2]),"+f"(d[3]) \
        : "r"(a0),"r"(a1),"r"(a2),"r"(a3),"r"(b0),"r"(b1))

__device__ __forceinline__ void cpa16(uint32_t dst, const void* src) {
    asm volatile("cp.async.ca.shared.global [%0], [%1], 16;\n" :: "r"(dst), "l"(src));
}
__device__ __forceinline__ void cpcommit() { asm volatile("cp.async.commit_group;\n" ::); }
template<int N> __device__ __forceinline__ void cpwait() {
    asm volatile("cp.async.wait_group %0;\n" :: "n"(N));
}

// ======================= prep kernels =======================
// Wqkv -> [n=3072][k=1024] fp16 hi/lo.  n -> (mat, h, d)
__global__ void prep_qkv_h(const float* __restrict__ Wq, const float* __restrict__ Wk,
                           const float* __restrict__ Wv,
                           __half* __restrict__ Th, __half* __restrict__ Tl) {
    __shared__ float t[32][33];
    int k0 = blockIdx.x * 32;
    int nt = blockIdx.y;                 // 0..95
    int mat = nt >> 5, wi = nt & 31;
    int h = wi >> 1, d0 = (wi & 1) * 32;
    const float* W = (mat == 0) ? Wq : (mat == 1) ? Wk : Wv;
    int tx = threadIdx.x, ty = threadIdx.y;
    t[ty][tx] = W[h * 65536 + (k0 + ty) * 64 + d0 + tx];
    __syncthreads();
    int n = mat * 1024 + h * 64 + d0 + ty;
    float w = t[tx][ty];
    __half hi = __float2half_rn(w);
    Th[(size_t)n * CC + k0 + tx] = hi;
    Tl[(size_t)n * CC + k0 + tx] = __float2half_rn(w - __half2float(hi));
}

// W[K][N] f32 -> Wt[N][K] fp16
__global__ void prep_t(const float* __restrict__ W, __half* __restrict__ Wt, int K, int N) {
    __shared__ float t[32][33];
    int n0 = blockIdx.x * 32, k0 = blockIdx.y * 32;
    int tx = threadIdx.x, ty = threadIdx.y;
    t[ty][tx] = W[(size_t)(k0 + ty) * N + n0 + tx];
    __syncthreads();
    Wt[(size_t)(n0 + ty) * K + k0 + tx] = __float2half_rn(t[tx][ty]);
}

// ======================= LayerNorm (f32 in, fp16 out) =======================
template<int MODE>   // 2 = hi+lo, 1 = hi only
__global__ void ln_h(const float* __restrict__ X, const float* __restrict__ gam,
                     const float* __restrict__ bet,
                     __half* __restrict__ Yh, __half* __restrict__ Yl) {
    int row = blockIdx.x;
    const float* xr = X + (size_t)row * CC;
    int tid = threadIdx.x;
    float4 v = *(const float4*)(xr + tid * 4);
    float s  = v.x + v.y + v.z + v.w;
    float ss = v.x*v.x + v.y*v.y + v.z*v.z + v.w*v.w;
    #pragma unroll
    for (int off = 16; off >= 1; off >>= 1) {
        s  += __shfl_xor_sync(0xffffffffu, s,  off);
        ss += __shfl_xor_sync(0xffffffffu, ss, off);
    }
    __shared__ float sb[8], ssb[8];
    if ((tid & 31) == 0) { sb[tid >> 5] = s; ssb[tid >> 5] = ss; }
    __syncthreads();
    s = 0.f; ss = 0.f;
    #pragma unroll
    for (int w = 0; w < 8; w++) { s += sb[w]; ss += ssb[w]; }
    float mu  = s * (1.0f / CC);
    float var = ss * (1.0f / CC) - mu * mu;
    float rs  = rsqrtf(var + 1e-5f);
    float4 gv = *(const float4*)(gam + tid * 4);
    float4 bv = *(const float4*)(bet + tid * 4);
    float y[4];
    y[0] = (v.x - mu) * rs * gv.x + bv.x;
    y[1] = (v.y - mu) * rs * gv.y + bv.y;
    y[2] = (v.z - mu) * rs * gv.z + bv.z;
    y[3] = (v.w - mu) * rs * gv.w + bv.w;
    __half h[4];
    #pragma unroll
    for (int i = 0; i < 4; i++) h[i] = __float2half_rn(y[i]);
    int off = row * CC + tid * 4;
    *(half2*)(Yh + off)     = __halves2half2(h[0], h[1]);
    *(half2*)(Yh + off + 2) = __halves2half2(h[2], h[3]);
    if (MODE == 2) {
        __half lo[4];
        #pragma unroll
        for (int i = 0; i < 4; i++) lo[i] = __float2half_rn(y[i] - __half2float(h[i]));
        *(half2*)(Yl + off)     = __halves2half2(lo[0], lo[1]);
        *(half2*)(Yl + off + 2) = __halves2half2(lo[2], lo[3]);
    }
}

// ============ fp16 GEMM: A[M][K] half, Bt[N][K] half, 128x128x32 tiles ============
#define GP 40                 // smem pitch in halves
#define GST 5120              // stage stride in halves (128*40)
template<bool RELU, bool RESID, bool OUTH>
__global__ __launch_bounds__(256) void gemm_h(
        const __half* __restrict__ A, const __half* __restrict__ Bt,
        const float* __restrict__ bias, const float* __restrict__ resid,
        void* __restrict__ Cv, int M, int N, int K) {
    __shared__ __half As[2][GST];
    __shared__ __half Bs[2][GST];
    int tid = threadIdx.x, l = tid & 31, warp = tid >> 5;
    int wy = warp >> 2, wx = warp & 3, lr = l >> 2, lc = l & 3;
    int m0 = blockIdx.y * 128, n0 = blockIdx.x * 128;
    int a_row = (l & 7) + ((l >> 3) & 1) * 8, a_k = (l >> 4) * 8;
    int b_row = (l & 7) + ((l >> 4) & 1) * 8, b_k = ((l >> 3) & 1) * 8;
    float acc[4][4][4];
    #pragma unroll
    for (int i = 0; i < 4; i++)
        #pragma unroll
        for (int j = 0; j < 4; j++)
            #pragma unroll
            for (int f = 0; f < 4; f++) acc[i][j][f] = 0.f;
    uint32_t sA = smem_u32(As), sB = smem_u32(Bs);
    int r1c = tid >> 2, g1c = tid & 3;                 // chunk c = tid
    int r2c = (tid + 256) >> 2, g2c = tid & 3;         // chunk c = tid+256
    const int NT = K >> 5;
    {
        uint32_t o1 = (uint32_t)((r1c*GP + g1c*8) * 2);
        uint32_t o2 = (uint32_t)((r2c*GP + g2c*8) * 2);
        cpa16(sA + o1, A + (size_t)(m0 + r1c) * K + g1c*8);
        cpa16(sA + o2, A + (size_t)(m0 + r2c) * K + g2c*8);
        cpa16(sB + o1, Bt + (size_t)(n0 + r1c) * K + g1c*8);
        cpa16(sB + o2, Bt + (size_t)(n0 + r2c) * K + g2c*8);
        cpcommit();
    }
    for (int kt = 0; kt < NT; kt++) {
        int st = kt & 1;
        if (kt + 1 < NT) {
            int nx = (kt + 1) & 1, k0 = (kt + 1) * 32;
            uint32_t o1 = (uint32_t)((nx*GST + r1c*GP + g1c*8) * 2);
            uint32_t o2 = (uint32_t)((nx*GST + r2c*GP + g2c*8) * 2);
            cpa16(sA + o1, A + (size_t)(m0 + r1c) * K + k0 + g1c*8);
            cpa16(sA + o2, A + (size_t)(m0 + r2c) * K + k0 + g2c*8);
            cpa16(sB + o1, Bt + (size_t)(n0 + r1c) * K + k0 + g1c*8);
            cpa16(sB + o2, Bt + (size_t)(n0 + r2c) * K + k0 + g2c*8);
            cpcommit();
            cpwait<1>();
        } else cpwait<0>();
        __syncthreads();
        #pragma unroll
        for (int ks = 0; ks < 2; ks++) {
            uint32_t af[4][4], bf[4][2];
            #pragma unroll
            for (int mi = 0; mi < 4; mi++) {
                uint32_t ad = sA + (uint32_t)((st*GST + (wy*64 + mi*16 + a_row)*GP
                                               + ks*16 + a_k) * 2);
                LDM_X4(af[mi][0], af[mi][1], af[mi][2], af[mi][3], ad);
            }
            #pragma unroll
            for (int nb = 0; nb < 2; nb++) {
                uint32_t ad = sB + (uint32_t)((st*GST + (wx*32 + nb*16 + b_row)*GP
                                               + ks*16 + b_k) * 2);
                uint32_t q0,q1,q2,q3;
                LDM_X4(q0,q1,q2,q3, ad);
                bf[nb*2][0]=q0; bf[nb*2][1]=q1; bf[nb*2+1][0]=q2; bf[nb*2+1][1]=q3;
            }
            #pragma unroll
            for (int mi = 0; mi < 4; mi++)
                #pragma unroll
                for (int nj = 0; nj < 4; nj++)
                    MMA_F16(acc[mi][nj], af[mi][0],af[mi][1],af[mi][2],af[mi][3],
                            bf[nj][0], bf[nj][1]);
        }
        __syncthreads();
    }
    #pragma unroll
    for (int mi = 0; mi < 4; mi++) {
        #pragma unroll
        for (int nj = 0; nj < 4; nj++) {
            int row = m0 + wy*64 + mi*16 + lr;
            int col = n0 + wx*32 + nj*8 + 2*lc;
            float b0 = bias[col], b1 = bias[col+1];
            float v0 = acc[mi][nj][0] + b0, v1 = acc[mi][nj][1] + b1;
            float v2 = acc[mi][nj][2] + b0, v3 = acc[mi][nj][3] + b1;
            if (RESID) {
                float2 q0 = *(const float2*)(resid + (size_t)row * N + col);
                float2 q1 = *(const float2*)(resid + (size_t)(row+8) * N + col);
                v0 += q0.x; v1 += q0.y; v2 += q1.x; v3 += q1.y;
            }
            if (RELU) {
                v0 = fmaxf(v0, 0.f); v1 = fmaxf(v1, 0.f);
                v2 = fmaxf(v2, 0.f); v3 = fmaxf(v3, 0.f);
            }
            if (OUTH) {
                __half* C = (__half*)Cv;
                *(half2*)(C + (size_t)row * N + col)     = __floats2half2_rn(v0, v1);
                *(half2*)(C + (size_t)(row+8) * N + col) = __floats2half2_rn(v2, v3);
            } else {
                float* C = (float*)Cv;
                *(float2*)(C + (size_t)row * N + col)     = make_float2(v0, v1);
                *(float2*)(C + (size_t)(row+8) * N + col) = make_float2(v2, v3);
            }
        }
    }
}

// ============ QKV GEMM: 3-term fp16 split, split epilogue ============
__global__ __launch_bounds__(256) void gemm_qkv_h(
        const __half* __restrict__ Ah_, const __half* __restrict__ Al_,
        const __half* __restrict__ Bh_, const __half* __restrict__ Bl_,
        const float* __restrict__ bq, const float* __restrict__ bk_,
        const float* __restrict__ bv_,
        __half* __restrict__ qh, __half* __restrict__ ql,
        __half* __restrict__ kh, __half* __restrict__ kl,
        __half* __restrict__ vh) {
    extern __shared__ __half smq[];
    __half* Ah = smq;            // [2][5120]
    __half* Al = smq + 10240;
    __half* Bh = smq + 20480;
    __half* Bl = smq + 30720;
    const int K = CC;
    int tid = threadIdx.x, l = tid & 31, warp = tid >> 5;
    int wy = warp >> 2, wx = warp & 3, lr = l >> 2, lc = l & 3;
    int m0 = blockIdx.y * 128, n0 = blockIdx.x * 128;
    int a_row = (l & 7) + ((l >> 3) & 1) * 8, a_k = (l >> 4) * 8;
    int b_row = (l & 7) + ((l >> 4) & 1) * 8, b_k = ((l >> 3) & 1) * 8;
    float acc[4][4][4];
    #pragma unroll
    for (int i = 0; i < 4; i++)
        #pragma unroll
        for (int j = 0; j < 4; j++)
            #pragma unroll
            for (int f = 0; f < 4; f++) acc[i][j][f] = 0.f;
    uint32_t sAh = smem_u32(Ah), sAl = smem_u32(Al);
    uint32_t sBh = smem_u32(Bh), sBl = smem_u32(Bl);
    int r1c = tid >> 2, g1c = tid & 3;
    int r2c = (tid + 256) >> 2;
    const int NT = K >> 5;
    auto pf = [&](int kt, int st) {
        int k0 = kt * 32;
        uint32_t o1 = (uint32_t)((st*GST + r1c*GP + g1c*8) * 2);
        uint32_t o2 = (uint32_t)((st*GST + r2c*GP + g1c*8) * 2);
        const __half* a1 = Ah_ + (size_t)(m0 + r1c) * K + k0 + g1c*8;
        const __half* a2 = Ah_ + (size_t)(m0 + r2c) * K + k0 + g1c*8;
        const __half* b1 = Bh_ + (size_t)(n0 + r1c) * K + k0 + g1c*8;
        const __half* b2 = Bh_ + (size_t)(n0 + r2c) * K + k0 + g1c*8;
        cpa16(sAh + o1, a1); cpa16(sAh + o2, a2);
        cpa16(sBh + o1, b1); cpa16(sBh + o2, b2);
        cpa16(sAl + o1, Al_ + (size_t)(m0 + r1c) * K + k0 + g1c*8);
        cpa16(sAl + o2, Al_ + (size_t)(m0 + r2c) * K + k0 + g1c*8);
        cpa16(sBl + o1, Bl_ + (size_t)(n0 + r1c) * K + k0 + g1c*8);
        cpa16(sBl + o2, Bl_ + (size_t)(n0 + r2c) * K + k0 + g1c*8);
    };
    pf(0, 0); cpcommit();
    for (int kt = 0; kt < NT; kt++) {
        int st = kt & 1;
        if (kt + 1 < NT) { pf(kt+1, (kt+1)&1); cpcommit(); cpwait<1>(); }
        else cpwait<0>();
        __syncthreads();
        #pragma unroll
        for (int ks = 0; ks < 2; ks++) {
            uint32_t afh[4][4], afl[4][4];
            #pragma unroll
            for (int mi = 0; mi < 4; mi++) {
                uint32_t ao = (uint32_t)((st*GST + (wy*64 + mi*16 + a_row)*GP
                                          + ks*16 + a_k) * 2);
                LDM_X4(afh[mi][0], afh[mi][1], afh[mi][2], afh[mi][3], sAh + ao);
                LDM_X4(afl[mi][0], afl[mi][1], afl[mi][2], afl[mi][3], sAl + ao);
            }
            #pragma unroll
            for (int nb = 0; nb < 2; nb++) {
                uint32_t bo = (uint32_t)((st*GST + (wx*32 + nb*16 + b_row)*GP
                                          + ks*16 + b_k) * 2);
                uint32_t h0,h1,h2,h3, e0,e1,e2,e3;
                LDM_X4(h0,h1,h2,h3, sBh + bo);
                LDM_X4(e0,e1,e2,e3, sBl + bo);
                #pragma unroll
                for (int mi = 0; mi < 4; mi++) {
                    int nj = nb * 2;
                    MMA_F16(acc[mi][nj], afh[mi][0],afh[mi][1],afh[mi][2],afh[mi][3], e0,e1);
                    MMA_F16(acc[mi][nj], afl[mi][0],afl[mi][1],afl[mi][2],afl[mi][3], h0,h1);
                    MMA_F16(acc[mi][nj], afh[mi][0],afh[mi][1],afh[mi][2],afh[mi][3], h0,h1);
                    MMA_F16(acc[mi][nj+1], afh[mi][0],afh[mi][1],afh[mi][2],afh[mi][3], e2,e3);
                    MMA_F16(acc[mi][nj+1], afl[mi][0],afl[mi][1],afl[mi][2],afl[mi][3], h2,h3);
                    MMA_F16(acc[mi][nj+1], afh[mi][0],afh[mi][1],afh[mi][2],afh[mi][3], h2,h3);
                }
            }
        }
        __syncthreads();
    }
    int mat = n0 >> 10, rem0 = n0 & 1023;
    const float* bias = (mat == 0) ? bq : (mat == 1) ? bk_ : bv_;
    float sc = (mat == 0) ? 8.f : 1.f;
    #pragma unroll
    for (int mi = 0; mi < 4; mi++) {
        #pragma unroll
        for (int nj = 0; nj < 4; nj++) {
            int row = m0 + wy*64 + mi*16 + lr;
            int col = rem0 + wx*32 + nj*8 + 2*lc;
            float b0 = bias[col], b1 = bias[col+1];
            float v0 = (acc[mi][nj][0] + b0) * sc, v1 = (acc[mi][nj][1] + b1) * sc;
            float v2 = (acc[mi][nj][2] + b0) * sc, v3 = (acc[mi][nj][3] + b1) * sc;
            size_t i0 = (size_t)row * CC + col, i1 = (size_t)(row+8) * CC + col;
            if (mat == 2) {
                *(half2*)(vh + i0) = __floats2half2_rn(v0, v1);
                *(half2*)(vh + i1) = __floats2half2_rn(v2, v3);
            } else {
                __half* oh = (mat == 0) ? qh : kh;
                __half* ol = (mat == 0) ? ql : kl;
                __half h0 = __float2half_rn(v0), h1 = __float2half_rn(v1);
                __half h2 = __float2half_rn(v2), h3 = __float2half_rn(v3);
                *(half2*)(oh + i0) = __halves2half2(h0, h1);
                *(half2*)(oh + i1) = __halves2half2(h2, h3);
                *(half2*)(ol + i0) = __halves2half2(
                    __float2half_rn(v0 - __half2float(h0)),
                    __float2half_rn(v1 - __half2float(h1)));
                *(half2*)(ol + i1) = __halves2half2(
                    __float2half_rn(v2 - __half2float(h2)),
                    __float2half_rn(v3 - __half2float(h3)));
            }
        }
    }
}

// ================= fp16 tensor-core flash attention =================
// BR=128, BC=64, DH=64; 8 warps, warp owns 16 rows.  Q pre-scaled by 8.
// smem halves: Ph[128][72] @0, Kh[2][64][72] @9216, Kl @18432, Vs[2][64][72] @27648
#define ATSMH (36864*2)
__global__ __launch_bounds__(256, 1) void attn_h(
        const __half* __restrict__ Qh_, const __half* __restrict__ Ql_,
        const __half* __restrict__ Kh_, const __half* __restrict__ Kl_,
        const __half* __restrict__ V_, __half* __restrict__ O_) {
    extern __shared__ __half sma[];
    __half* Ph = sma;
    __half* Kh = sma + 9216;
    __half* Kl = sma + 18432;
    __half* Vs = sma + 27648;
    uint32_t sPh = smem_u32(Ph), sKh = smem_u32(Kh), sKl = smem_u32(Kl), sVs = smem_u32(Vs);
    int tid = threadIdx.x, lane = tid & 31, warp = tid >> 5;
    int lr = lane >> 2, lc = lane & 3;
    int r0 = blockIdx.x * 128;
    int h  = blockIdx.y;
    int b  = blockIdx.z;
    size_t base = (size_t)b * TT * CC + h * DHH;

    int a_row = (lane & 7) + ((lane >> 3) & 1) * 8, a_k = (lane >> 4) * 8;
    int b_row = (lane & 7) + ((lane >> 4) & 1) * 8, b_k = ((lane >> 3) & 1) * 8;
    int v_row = (lane & 7) + ((lane >> 3) & 1) * 8, v_d = (lane >> 4) * 8;

    int c1r = tid >> 3, c1g = tid & 7;
    int c2r = (tid + 256) >> 3;
    auto pfkv = [&](int t, int st) {
        int s0 = t * 64;
        uint32_t o1 = (uint32_t)((st*4608 + c1r*72 + c1g*8) * 2);
        uint32_t o2 = (uint32_t)((st*4608 + c2r*72 + c1g*8) * 2);
        size_t g1 = base + (size_t)(s0 + c1r) * CC + c1g*8;
        size_t g2 = base + (size_t)(s0 + c2r) * CC + c1g*8;
        cpa16(sKh + o1, Kh_ + g1); cpa16(sKh + o2, Kh_ + g2);
        cpa16(sKl + o1, Kl_ + g1); cpa16(sKl + o2, Kl_ + g2);
        cpa16(sVs + o1, V_ + g1);  cpa16(sVs + o2, V_ + g2);
    };
    pfkv(0, 0); cpcommit();

    // ---- load Q fragments (hi then lo) through Ph ----
    uint32_t qfh[4][4], qfl[4][4];
    #pragma unroll
    for (int pass = 0; pass < 2; pass++) {
        const __half* src = pass ? Ql_ : Qh_;
        #pragma unroll
        for (int i = 0; i < 4; i++) {
            int c = tid + 256 * i;         // < 1024
            int row = c >> 3, cg = c & 7;
            *(uint4*)(Ph + row*72 + cg*8) =
                *(const uint4*)(src + base + (size_t)(r0 + row) * CC + cg*8);
        }
        __syncthreads();
        #pragma unroll
        for (int kt = 0; kt < 4; kt++) {
            uint32_t ad = sPh + (uint32_t)(((16*warp + a_row)*72 + kt*16 + a_k) * 2);
            if (pass) { LDM_X4(qfl[kt][0], qfl[kt][1], qfl[kt][2], qfl[kt][3], ad); }
            else      { LDM_X4(qfh[kt][0], qfh[kt][1], qfh[kt][2], qfh[kt][3], ad); }
        }
        __syncthreads();
    }

    float oacc[8][4];
    #pragma unroll
    for (int dj = 0; dj < 8; dj++)
        #pragma unroll
        for (int f = 0; f < 4; f++) oacc[dj][f] = 0.f;
    float m0 = -3e38f, m1 = -3e38f, l0 = 0.f, l1 = 0.f;

    const int NTL = TT / 64;  // 32
    for (int t = 0; t < NTL; t++) {
        int st = t & 1;
        if (t + 1 < NTL) { pfkv(t+1, (t+1)&1); cpcommit(); cpwait<1>(); }
        else cpwait<0>();
        __syncthreads();

        // ---- S = (8Q)·K^T, 3-term fp16 ----
        float s[8][4];
        #pragma unroll
        for (int nj = 0; nj < 8; nj++)
            #pragma unroll
            for (int f = 0; f < 4; f++) s[nj][f] = 0.f;
        #pragma unroll
        for (int kt = 0; kt < 4; kt++) {
            #pragma unroll
            for (int nb = 0; nb < 4; nb++) {
                uint32_t off = (uint32_t)((st*4608 + (nb*16 + b_row)*72
                                           + kt*16 + b_k) * 2);
                uint32_t h0,h1,h2,h3, e0,e1,e2,e3;
                LDM_X4(h0,h1,h2,h3, sKh + off);
                LDM_X4(e0,e1,e2,e3, sKl + off);
                int nj = nb * 2;
                MMA_F16(s[nj], qfh[kt][0],qfh[kt][1],qfh[kt][2],qfh[kt][3], e0,e1);
                MMA_F16(s[nj], qfl[kt][0],qfl[kt][1],qfl[kt][2],qfl[kt][3], h0,h1);
                MMA_F16(s[nj], qfh[kt][0],qfh[kt][1],qfh[kt][2],qfh[kt][3], h0,h1);
                MMA_F16(s[nj+1], qfh[kt][0],qfh[kt][1],qfh[kt][2],qfh[kt][3], e2,e3);
                MMA_F16(s[nj+1], qfl[kt][0],qfl[kt][1],qfl[kt][2],qfl[kt][3], h2,h3);
                MMA_F16(s[nj+1], qfh[kt][0],qfh[kt][1],qfh[kt][2],qfh[kt][3], h2,h3);
            }
        }
        // ---- online softmax ----
        float mt0 = -3e38f, mt1 = -3e38f;
        #pragma unroll
        for (int nj = 0; nj < 8; nj++) {
            mt0 = fmaxf(mt0, fmaxf(s[nj][0], s[nj][1]));
            mt1 = fmaxf(mt1, fmaxf(s[nj][2], s[nj][3]));
        }
        mt0 = fmaxf(mt0, __shfl_xor_sync(0xffffffffu, mt0, 1));
        mt0 = fmaxf(mt0, __shfl_xor_sync(0xffffffffu, mt0, 2));
        mt1 = fmaxf(mt1, __shfl_xor_sync(0xffffffffu, mt1, 1));
        mt1 = fmaxf(mt1, __shfl_xor_sync(0xffffffffu, mt1, 2));
        float mn0 = fmaxf(m0, mt0), mn1 = fmaxf(m1, mt1);
        float al0 = __expf(m0 - mn0), al1 = __expf(m1 - mn1);
        float ps0 = 0.f, ps1 = 0.f;
        int pr0 = (16*warp + lr) * 72, pr1 = (16*warp + 8 + lr) * 72;
        #pragma unroll
        for (int nj = 0; nj < 8; nj++) {
            float p0 = __expf(s[nj][0] - mn0);
            float p1 = __expf(s[nj][1] - mn0);
            float p2 = __expf(s[nj][2] - mn1);
            float p3 = __expf(s[nj][3] - mn1);
            ps0 += p0 + p1; ps1 += p2 + p3;
            *(half2*)(Ph + pr0 + nj*8 + 2*lc) = __floats2half2_rn(p0, p1);
            *(half2*)(Ph + pr1 + nj*8 + 2*lc) = __floats2half2_rn(p2, p3);
        }
        ps0 += __shfl_xor_sync(0xffffffffu, ps0, 1);
        ps0 += __shfl_xor_sync(0xffffffffu, ps0, 2);
        ps1 += __shfl_xor_sync(0xffffffffu, ps1, 1);
        ps1 += __shfl_xor_sync(0xffffffffu, ps1, 2);
        l0 = l0 * al0 + ps0;
        l1 = l1 * al1 + ps1;
        m0 = mn0; m1 = mn1;
        #pragma unroll
        for (int dj = 0; dj < 8; dj++) {
            oacc[dj][0] *= al0; oacc[dj][1] *= al0;
            oacc[dj][2] *= al1; oacc[dj][3] *= al1;
        }
        __syncwarp();
        // ---- O += P·V ----
        #pragma unroll
        for (int kt = 0; kt < 4; kt++) {
            uint32_t pa0,pa1,pa2,pa3;
            LDM_X4(pa0,pa1,pa2,pa3,
                   sPh + (uint32_t)(((16*warp + a_row)*72 + kt*16 + a_k) * 2));
            #pragma unroll
            for (int dp = 0; dp < 4; dp++) {
                uint32_t v0,v1,v2,v3;
                uint32_t ad = sVs + (uint32_t)((st*4608 + (kt*16 + v_row)*72
                                                + dp*16 + v_d) * 2);
                LDM_X4T(v0,v1,v2,v3, ad);
                MMA_F16(oacc[dp*2],   pa0,pa1,pa2,pa3, v0,v1);
                MMA_F16(oacc[dp*2+1], pa0,pa1,pa2,pa3, v2,v3);
            }
        }
        __syncthreads();
    }
    // ---- epilogue: O/l -> fp16 ----
    float inv0 = 1.f / l0, inv1 = 1.f / l1;
    int row0 = r0 + 16*warp + lr, row1 = row0 + 8;
    #pragma unroll
    for (int dj = 0; dj < 8; dj++) {
        int col = dj*8 + 2*lc;
        *(half2*)(O_ + base + (size_t)row0 * CC + col) =
            __floats2half2_rn(oacc[dj][0]*inv0, oacc[dj][1]*inv0);
        *(half2*)(O_ + base + (size_t)row1 * CC + col) =
            __floats2half2_rn(oacc[dj][2]*inv1, oacc[dj][3]*inv1);
    }
}

// ========================= launch =========================
extern "C" void kernel_launch(void* const* d_in, const int* in_sizes, int n_in,
                              void* d_out, int out_size) {
    const float* x     = (const float*)d_in[0];
    const float* Wq    = (const float*)d_in[1];
    const float* bq    = (const float*)d_in[2];
    const float* Wk    = (const float*)d_in[3];
    const float* bk    = (const float*)d_in[4];
    const float* Wv    = (const float*)d_in[5];
    const float* bv    = (const float*)d_in[6];
    const float* Wo    = (const float*)d_in[7];
    const float* bo    = (const float*)d_in[8];
    const float* ln1g  = (const float*)d_in[9];
    const float* ln1b  = (const float*)d_in[10];
    const float* ln2g  = (const float*)d_in[11];
    const float* ln2b  = (const float*)d_in[12];
    const float* W1    = (const float*)d_in[13];
    const float* b1    = (const float*)d_in[14];
    const float* W2    = (const float*)d_in[15];
    const float* b2    = (const float*)d_in[16];
    float* out = (float*)d_out;

    __half *xnh,*xnl,*qh,*ql,*kh,*kl,*vh,*oh,*x2h,*ffh,*wqh,*wql,*wot,*w1t,*w2t;
    float *x1;
    cudaGetSymbolAddress((void**)&xnh, g_xnh);
    cudaGetSymbolAddress((void**)&xnl, g_xnl);
    cudaGetSymbolAddress((void**)&qh,  g_qhh);
    cudaGetSymbolAddress((void**)&ql,  g_qll);
    cudaGetSymbolAddress((void**)&kh,  g_khh);
    cudaGetSymbolAddress((void**)&kl,  g_kll);
    cudaGetSymbolAddress((void**)&vh,  g_vhh);
    cudaGetSymbolAddress((void**)&oh,  g_ohh);
    cudaGetSymbolAddress((void**)&x2h, g_x2h);
    cudaGetSymbolAddress((void**)&ffh, g_ffh);
    cudaGetSymbolAddress((void**)&x1,  g_x1);
    cudaGetSymbolAddress((void**)&wqh, g_wqh);
    cudaGetSymbolAddress((void**)&wql, g_wql);
    cudaGetSymbolAddress((void**)&wot, g_wot);
    cudaGetSymbolAddress((void**)&w1t, g_w1t);
    cudaGetSymbolAddress((void**)&w2t, g_w2t);

    const int QKV_SMEM = 40960 * 2;   // 81920 B
    cudaFuncSetAttribute(gemm_qkv_h, cudaFuncAttributeMaxDynamicSharedMemorySize, QKV_SMEM);
    cudaFuncSetAttribute(attn_h, cudaFuncAttributeMaxDynamicSharedMemorySize, ATSMH);

    // weight prep
    prep_qkv_h<<<dim3(32, 96), dim3(32, 32)>>>(Wq, Wk, Wv, wqh, wql);
    prep_t<<<dim3(32, 32),  dim3(32, 32)>>>(Wo, wot, 1024, 1024);
    prep_t<<<dim3(128, 32), dim3(32, 32)>>>(W1, w1t, 1024, 4096);
    prep_t<<<dim3(32, 128), dim3(32, 32)>>>(W2, w2t, 4096, 1024);

    // 1) LN1 (hi+lo fp16)
    ln_h<2><<<MM, 256>>>(x, ln1g, ln1b, xnh, xnl);
    // 2) QKV (3-term fp16)
    gemm_qkv_h<<<dim3(24, 64), 256, QKV_SMEM>>>(xnh, xnl, wqh, wql,
                                                bq, bk, bv, qh, ql, kh, kl, vh);
    // 3) attention (fp16 TC flash)
    attn_h<<<dim3(TT/128, HH, BB), 256, ATSMH>>>(qh, ql, kh, kl, vh, oh);
    // 4) out proj + residual -> x1 (fp32)
    gemm_h<false, true, false><<<dim3(8, 64), 256>>>(oh, wot, bo, x, (void*)x1, MM, CC, CC);
    // 5) LN2 (fp16 hi)
    ln_h<1><<<MM, 256>>>(x1, ln2g, ln2b, x2h, nullptr);
    // 6) FFN1 (relu, fp16 out)
    gemm_h<true, false, true><<<dim3(32, 64), 256>>>(x2h, w1t, b1, nullptr, (void*)ffh, MM, DFF, CC);
    // 7) FFN2 + residual -> out (fp32)
    gemm_h<false, true, false><<<dim3(8, 64), 256>>>(ffh, w2t, b2, x1, (void*)out, MM, CC, DFF);
}

// round 7
// speedup vs baseline: 4.6590x; 1.0141x over previous
#include <cuda_runtime.h>
#include <cuda_fp16.h>
#include <math.h>
#include <stdint.h>

#define BB 4
#define TT 2048
#define CC 1024
#define HH 16
#define DHH 64
#define DFF 4096
#define MM (BB*TT)   /* 8192 */

// -------- scratch (device globals; no allocation) --------
__device__ __half g_xnh[(size_t)MM*CC];
__device__ __half g_xnl[(size_t)MM*CC];
__device__ __half g_qhh[(size_t)MM*CC];
__device__ __half g_qll[(size_t)MM*CC];
__device__ __half g_khh[(size_t)MM*CC];
__device__ __half g_kll[(size_t)MM*CC];
__device__ __half g_vhh[(size_t)MM*CC];
__device__ __half g_ohh[(size_t)MM*CC];
__device__ __half g_x2h[(size_t)MM*CC];
__device__ __half g_ffh[(size_t)MM*DFF];
__device__ float  g_x1 [(size_t)MM*CC];
__device__ __half g_wqh[(size_t)CC*3072];
__device__ __half g_wql[(size_t)CC*3072];
__device__ __half g_wot[(size_t)CC*CC];
__device__ __half g_w1t[(size_t)CC*DFF];
__device__ __half g_w2t[(size_t)DFF*CC];

// ======================= helpers =======================
__device__ __forceinline__ uint32_t smem_u32(const void* p) {
    return (uint32_t)__cvta_generic_to_shared(p);
}
#define LDM_X4(r0,r1,r2,r3, addr) \
    asm volatile("ldmatrix.sync.aligned.m8n8.x4.shared.b16 {%0,%1,%2,%3},[%4];" \
        : "=r"(r0),"=r"(r1),"=r"(r2),"=r"(r3) : "r"(addr))
#define LDM_X4T(r0,r1,r2,r3, addr) \
    asm volatile("ldmatrix.sync.aligned.m8n8.x4.trans.shared.b16 {%0,%1,%2,%3},[%4];" \
        : "=r"(r0),"=r"(r1),"=r"(r2),"=r"(r3) : "r"(addr))
#define MMA_F16(d, a0,a1,a2,a3, b0,b1) \
    asm volatile("mma.sync.aligned.m16n8k16.row.col.f32.f16.f16.f32 " \
        "{%0,%1,%2,%3},{%4,%5,%6,%7},{%8,%9},{%0,%1,%2,%3};" \
        : "+f"(d[0]),"+f"(d[1]),"+f"(d[2]),"+f"(d[3]) \
        : "r"(a0),"r"(a1),"r"(a2),"r"(a3),"r"(b0),"r"(b1))

__device__ __forceinline__ void cpa16(uint32_t dst, const void* src) {
    asm volatile("cp.async.ca.shared.global [%0], [%1], 16;\n" :: "r"(dst), "l"(src));
}
__device__ __forceinline__ void cpcommit() { asm volatile("cp.async.commit_group;\n" ::); }
template<int N> __device__ __forceinline__ void cpwait() {
    asm volatile("cp.async.wait_group %0;\n" :: "n"(N));
}

// ======================= prep kernels =======================
__global__ void prep_qkv_h(const float* __restrict__ Wq, const float* __restrict__ Wk,
                           const float* __restrict__ Wv,
                           __half* __restrict__ Th, __half* __restrict__ Tl) {
    __shared__ float t[32][33];
    int k0 = blockIdx.x * 32;
    int nt = blockIdx.y;                 // 0..95
    int mat = nt >> 5, wi = nt & 31;
    int h = wi >> 1, d0 = (wi & 1) * 32;
    const float* W = (mat == 0) ? Wq : (mat == 1) ? Wk : Wv;
    int tx = threadIdx.x, ty = threadIdx.y;
    t[ty][tx] = W[h * 65536 + (k0 + ty) * 64 + d0 + tx];
    __syncthreads();
    int n = mat * 1024 + h * 64 + d0 + ty;
    float w = t[tx][ty];
    __half hi = __float2half_rn(w);
    Th[(size_t)n * CC + k0 + tx] = hi;
    Tl[(size_t)n * CC + k0 + tx] = __float2half_rn(w - __half2float(hi));
}

__global__ void prep_t(const float* __restrict__ W, __half* __restrict__ Wt, int K, int N) {
    __shared__ float t[32][33];
    int n0 = blockIdx.x * 32, k0 = blockIdx.y * 32;
    int tx = threadIdx.x, ty = threadIdx.y;
    t[ty][tx] = W[(size_t)(k0 + ty) * N + n0 + tx];
    __syncthreads();
    Wt[(size_t)(n0 + ty) * K + k0 + tx] = __float2half_rn(t[tx][ty]);
}

// ======================= LayerNorm (f32 in, fp16 out) =======================
template<int MODE>   // 2 = hi+lo, 1 = hi only
__global__ void ln_h(const float* __restrict__ X, const float* __restrict__ gam,
                     const float* __restrict__ bet,
                     __half* __restrict__ Yh, __half* __restrict__ Yl) {
    int row = blockIdx.x;
    const float* xr = X + (size_t)row * CC;
    int tid = threadIdx.x;
    float4 v = *(const float4*)(xr + tid * 4);
    float s  = v.x + v.y + v.z + v.w;
    float ss = v.x*v.x + v.y*v.y + v.z*v.z + v.w*v.w;
    #pragma unroll
    for (int off = 16; off >= 1; off >>= 1) {
        s  += __shfl_xor_sync(0xffffffffu, s,  off);
        ss += __shfl_xor_sync(0xffffffffu, ss, off);
    }
    __shared__ float sb[8], ssb[8];
    if ((tid & 31) == 0) { sb[tid >> 5] = s; ssb[tid >> 5] = ss; }
    __syncthreads();
    s = 0.f; ss = 0.f;
    #pragma unroll
    for (int w = 0; w < 8; w++) { s += sb[w]; ss += ssb[w]; }
    float mu  = s * (1.0f / CC);
    float var = ss * (1.0f / CC) - mu * mu;
    float rs  = rsqrtf(var + 1e-5f);
    float4 gv = *(const float4*)(gam + tid * 4);
    float4 bv = *(const float4*)(bet + tid * 4);
    float y[4];
    y[0] = (v.x - mu) * rs * gv.x + bv.x;
    y[1] = (v.y - mu) * rs * gv.y + bv.y;
    y[2] = (v.z - mu) * rs * gv.z + bv.z;
    y[3] = (v.w - mu) * rs * gv.w + bv.w;
    __half h[4];
    #pragma unroll
    for (int i = 0; i < 4; i++) h[i] = __float2half_rn(y[i]);
    int off = row * CC + tid * 4;
    *(half2*)(Yh + off)     = __halves2half2(h[0], h[1]);
    *(half2*)(Yh + off + 2) = __halves2half2(h[2], h[3]);
    if (MODE == 2) {
        __half lo[4];
        #pragma unroll
        for (int i = 0; i < 4; i++) lo[i] = __float2half_rn(y[i] - __half2float(h[i]));
        *(half2*)(Yl + off)     = __halves2half2(lo[0], lo[1]);
        *(half2*)(Yl + off + 2) = __halves2half2(lo[2], lo[3]);
    }
}

// ============ fp16 GEMM: A[M][K] half, Bt[N][K] half, 128x128x32 tiles ============
#define GP 40                 // smem pitch in halves
#define GST 5120              // stage stride in halves (128*40)
template<bool RELU, bool RESID, bool OUTH>
__global__ __launch_bounds__(256, 2) void gemm_h(
        const __half* __restrict__ A, const __half* __restrict__ Bt,
        const float* __restrict__ bias, const float* __restrict__ resid,
        void* __restrict__ Cv, int M, int N, int K) {
    __shared__ __half As[2][GST];
    __shared__ __half Bs[2][GST];
    int tid = threadIdx.x, l = tid & 31, warp = tid >> 5;
    int wy = warp >> 2, wx = warp & 3, lr = l >> 2, lc = l & 3;
    int m0 = blockIdx.y * 128, n0 = blockIdx.x * 128;
    int a_row = (l & 7) + ((l >> 3) & 1) * 8, a_k = (l >> 4) * 8;
    int b_row = (l & 7) + ((l >> 4) & 1) * 8, b_k = ((l >> 3) & 1) * 8;
    float acc[4][4][4];
    #pragma unroll
    for (int i = 0; i < 4; i++)
        #pragma unroll
        for (int j = 0; j < 4; j++)
            #pragma unroll
            for (int f = 0; f < 4; f++) acc[i][j][f] = 0.f;
    uint32_t sA = smem_u32(As), sB = smem_u32(Bs);
    int r1c = tid >> 2, g1c = tid & 3;
    int r2c = (tid + 256) >> 2, g2c = tid & 3;
    const int NT = K >> 5;
    {
        uint32_t o1 = (uint32_t)((r1c*GP + g1c*8) * 2);
        uint32_t o2 = (uint32_t)((r2c*GP + g2c*8) * 2);
        cpa16(sA + o1, A + (size_t)(m0 + r1c) * K + g1c*8);
        cpa16(sA + o2, A + (size_t)(m0 + r2c) * K + g2c*8);
        cpa16(sB + o1, Bt + (size_t)(n0 + r1c) * K + g1c*8);
        cpa16(sB + o2, Bt + (size_t)(n0 + r2c) * K + g2c*8);
        cpcommit();
    }
    for (int kt = 0; kt < NT; kt++) {
        int st = kt & 1;
        if (kt + 1 < NT) {
            int nx = (kt + 1) & 1, k0 = (kt + 1) * 32;
            uint32_t o1 = (uint32_t)((nx*GST + r1c*GP + g1c*8) * 2);
            uint32_t o2 = (uint32_t)((nx*GST + r2c*GP + g2c*8) * 2);
            cpa16(sA + o1, A + (size_t)(m0 + r1c) * K + k0 + g1c*8);
            cpa16(sA + o2, A + (size_t)(m0 + r2c) * K + k0 + g2c*8);
            cpa16(sB + o1, Bt + (size_t)(n0 + r1c) * K + k0 + g1c*8);
            cpa16(sB + o2, Bt + (size_t)(n0 + r2c) * K + k0 + g2c*8);
            cpcommit();
            cpwait<1>();
        } else cpwait<0>();
        __syncthreads();
        #pragma unroll
        for (int ks = 0; ks < 2; ks++) {
            uint32_t af[4][4], bf[4][2];
            #pragma unroll
            for (int mi = 0; mi < 4; mi++) {
                uint32_t ad = sA + (uint32_t)((st*GST + (wy*64 + mi*16 + a_row)*GP
                                               + ks*16 + a_k) * 2);
                LDM_X4(af[mi][0], af[mi][1], af[mi][2], af[mi][3], ad);
            }
            #pragma unroll
            for (int nb = 0; nb < 2; nb++) {
                uint32_t ad = sB + (uint32_t)((st*GST + (wx*32 + nb*16 + b_row)*GP
                                               + ks*16 + b_k) * 2);
                uint32_t q0,q1,q2,q3;
                LDM_X4(q0,q1,q2,q3, ad);
                bf[nb*2][0]=q0; bf[nb*2][1]=q1; bf[nb*2+1][0]=q2; bf[nb*2+1][1]=q3;
            }
            #pragma unroll
            for (int mi = 0; mi < 4; mi++)
                #pragma unroll
                for (int nj = 0; nj < 4; nj++)
                    MMA_F16(acc[mi][nj], af[mi][0],af[mi][1],af[mi][2],af[mi][3],
                            bf[nj][0], bf[nj][1]);
        }
        __syncthreads();
    }
    #pragma unroll
    for (int mi = 0; mi < 4; mi++) {
        #pragma unroll
        for (int nj = 0; nj < 4; nj++) {
            int row = m0 + wy*64 + mi*16 + lr;
            int col = n0 + wx*32 + nj*8 + 2*lc;
            float b0 = bias[col], b1 = bias[col+1];
            float v0 = acc[mi][nj][0] + b0, v1 = acc[mi][nj][1] + b1;
            float v2 = acc[mi][nj][2] + b0, v3 = acc[mi][nj][3] + b1;
            if (RESID) {
                float2 q0 = *(const float2*)(resid + (size_t)row * N + col);
                float2 q1 = *(const float2*)(resid + (size_t)(row+8) * N + col);
                v0 += q0.x; v1 += q0.y; v2 += q1.x; v3 += q1.y;
            }
            if (RELU) {
                v0 = fmaxf(v0, 0.f); v1 = fmaxf(v1, 0.f);
                v2 = fmaxf(v2, 0.f); v3 = fmaxf(v3, 0.f);
            }
            if (OUTH) {
                __half* C = (__half*)Cv;
                *(half2*)(C + (size_t)row * N + col)     = __floats2half2_rn(v0, v1);
                *(half2*)(C + (size_t)(row+8) * N + col) = __floats2half2_rn(v2, v3);
            } else {
                float* C = (float*)Cv;
                *(float2*)(C + (size_t)row * N + col)     = make_float2(v0, v1);
                *(float2*)(C + (size_t)(row+8) * N + col) = make_float2(v2, v3);
            }
        }
    }
}

// ============ QKV GEMM: 3-term fp16 split, split epilogue ============
__global__ __launch_bounds__(256) void gemm_qkv_h(
        const __half* __restrict__ Ah_, const __half* __restrict__ Al_,
        const __half* __restrict__ Bh_, const __half* __restrict__ Bl_,
        const float* __restrict__ bq, const float* __restrict__ bk_,
        const float* __restrict__ bv_,
        __half* __restrict__ qh, __half* __restrict__ ql,
        __half* __restrict__ kh, __half* __restrict__ kl,
        __half* __restrict__ vh) {
    extern __shared__ __half smq[];
    __half* Ah = smq;            // [2][5120]
    __half* Al = smq + 10240;
    __half* Bh = smq + 20480;
    __half* Bl = smq + 30720;
    const int K = CC;
    int tid = threadIdx.x, l = tid & 31, warp = tid >> 5;
    int wy = warp >> 2, wx = warp & 3, lr = l >> 2, lc = l & 3;
    int m0 = blockIdx.y * 128, n0 = blockIdx.x * 128;
    int a_row = (l & 7) + ((l >> 3) & 1) * 8, a_k = (l >> 4) * 8;
    int b_row = (l & 7) + ((l >> 4) & 1) * 8, b_k = ((l >> 3) & 1) * 8;
    float acc[4][4][4];
    #pragma unroll
    for (int i = 0; i < 4; i++)
        #pragma unroll
        for (int j = 0; j < 4; j++)
            #pragma unroll
            for (int f = 0; f < 4; f++) acc[i][j][f] = 0.f;
    uint32_t sAh = smem_u32(Ah), sAl = smem_u32(Al);
    uint32_t sBh = smem_u32(Bh), sBl = smem_u32(Bl);
    int r1c = tid >> 2, g1c = tid & 3;
    int r2c = (tid + 256) >> 2;
    const int NT = K >> 5;
    auto pf = [&](int kt, int st) {
        int k0 = kt * 32;
        uint32_t o1 = (uint32_t)((st*GST + r1c*GP + g1c*8) * 2);
        uint32_t o2 = (uint32_t)((st*GST + r2c*GP + g1c*8) * 2);
        cpa16(sAh + o1, Ah_ + (size_t)(m0 + r1c) * K + k0 + g1c*8);
        cpa16(sAh + o2, Ah_ + (size_t)(m0 + r2c) * K + k0 + g1c*8);
        cpa16(sBh + o1, Bh_ + (size_t)(n0 + r1c) * K + k0 + g1c*8);
        cpa16(sBh + o2, Bh_ + (size_t)(n0 + r2c) * K + k0 + g1c*8);
        cpa16(sAl + o1, Al_ + (size_t)(m0 + r1c) * K + k0 + g1c*8);
        cpa16(sAl + o2, Al_ + (size_t)(m0 + r2c) * K + k0 + g1c*8);
        cpa16(sBl + o1, Bl_ + (size_t)(n0 + r1c) * K + k0 + g1c*8);
        cpa16(sBl + o2, Bl_ + (size_t)(n0 + r2c) * K + k0 + g1c*8);
    };
    pf(0, 0); cpcommit();
    for (int kt = 0; kt < NT; kt++) {
        int st = kt & 1;
        if (kt + 1 < NT) { pf(kt+1, (kt+1)&1); cpcommit(); cpwait<1>(); }
        else cpwait<0>();
        __syncthreads();
        #pragma unroll
        for (int ks = 0; ks < 2; ks++) {
            uint32_t afh[4][4], afl[4][4];
            #pragma unroll
            for (int mi = 0; mi < 4; mi++) {
                uint32_t ao = (uint32_t)((st*GST + (wy*64 + mi*16 + a_row)*GP
                                          + ks*16 + a_k) * 2);
                LDM_X4(afh[mi][0], afh[mi][1], afh[mi][2], afh[mi][3], sAh + ao);
                LDM_X4(afl[mi][0], afl[mi][1], afl[mi][2], afl[mi][3], sAl + ao);
            }
            #pragma unroll
            for (int nb = 0; nb < 2; nb++) {
                uint32_t bo = (uint32_t)((st*GST + (wx*32 + nb*16 + b_row)*GP
                                          + ks*16 + b_k) * 2);
                uint32_t h0,h1,h2,h3, e0,e1,e2,e3;
                LDM_X4(h0,h1,h2,h3, sBh + bo);
                LDM_X4(e0,e1,e2,e3, sBl + bo);
                #pragma unroll
                for (int mi = 0; mi < 4; mi++) {
                    int nj = nb * 2;
                    MMA_F16(acc[mi][nj], afh[mi][0],afh[mi][1],afh[mi][2],afh[mi][3], e0,e1);
                    MMA_F16(acc[mi][nj], afl[mi][0],afl[mi][1],afl[mi][2],afl[mi][3], h0,h1);
                    MMA_F16(acc[mi][nj], afh[mi][0],afh[mi][1],afh[mi][2],afh[mi][3], h0,h1);
                    MMA_F16(acc[mi][nj+1], afh[mi][0],afh[mi][1],afh[mi][2],afh[mi][3], e2,e3);
                    MMA_F16(acc[mi][nj+1], afl[mi][0],afl[mi][1],afl[mi][2],afl[mi][3], h2,h3);
                    MMA_F16(acc[mi][nj+1], afh[mi][0],afh[mi][1],afh[mi][2],afh[mi][3], h2,h3);
                }
            }
        }
        __syncthreads();
    }
    int mat = n0 >> 10, rem0 = n0 & 1023;
    const float* bias = (mat == 0) ? bq : (mat == 1) ? bk_ : bv_;
    float sc = (mat == 0) ? 8.f : 1.f;
    #pragma unroll
    for (int mi = 0; mi < 4; mi++) {
        #pragma unroll
        for (int nj = 0; nj < 4; nj++) {
            int row = m0 + wy*64 + mi*16 + lr;
            int col = rem0 + wx*32 + nj*8 + 2*lc;
            float b0 = bias[col], b1 = bias[col+1];
            float v0 = (acc[mi][nj][0] + b0) * sc, v1 = (acc[mi][nj][1] + b1) * sc;
            float v2 = (acc[mi][nj][2] + b0) * sc, v3 = (acc[mi][nj][3] + b1) * sc;
            size_t i0 = (size_t)row * CC + col, i1 = (size_t)(row+8) * CC + col;
            if (mat == 2) {
                *(half2*)(vh + i0) = __floats2half2_rn(v0, v1);
                *(half2*)(vh + i1) = __floats2half2_rn(v2, v3);
            } else {
                __half* oh = (mat == 0) ? qh : kh;
                __half* ol = (mat == 0) ? ql : kl;
                __half h0 = __float2half_rn(v0), h1 = __float2half_rn(v1);
                __half h2 = __float2half_rn(v2), h3 = __float2half_rn(v3);
                *(half2*)(oh + i0) = __halves2half2(h0, h1);
                *(half2*)(oh + i1) = __halves2half2(h2, h3);
                *(half2*)(ol + i0) = __halves2half2(
                    __float2half_rn(v0 - __half2float(h0)),
                    __float2half_rn(v1 - __half2float(h1)));
                *(half2*)(ol + i1) = __halves2half2(
                    __float2half_rn(v2 - __half2float(h2)),
                    __float2half_rn(v3 - __half2float(h3)));
            }
        }
    }
}

// ================= fp16 tensor-core flash attention, BC=128 =================
// BR=128, BC=128, DH=64; 8 warps, warp owns 16 rows. Q pre-scaled by 8.
// smem halves: Ph[128][136] @0 (17408), Kh[2][128][72] @17408, Kl @35840, Vs @54272
#define PP 136
#define KSTG 9216
#define ATSMH (72704*2)
__global__ __launch_bounds__(256, 1) void attn_h(
        const __half* __restrict__ Qh_, const __half* __restrict__ Ql_,
        const __half* __restrict__ Kh_, const __half* __restrict__ Kl_,
        const __half* __restrict__ V_, __half* __restrict__ O_) {
    extern __shared__ __half sma[];
    __half* Ph = sma;
    __half* Kh = sma + 17408;
    __half* Kl = sma + 35840;
    __half* Vs = sma + 54272;
    uint32_t sPh = smem_u32(Ph), sKh = smem_u32(Kh), sKl = smem_u32(Kl), sVs = smem_u32(Vs);
    int tid = threadIdx.x, lane = tid & 31, warp = tid >> 5;
    int lr = lane >> 2, lc = lane & 3;
    int r0 = blockIdx.x * 128;
    int h  = blockIdx.y;
    int b  = blockIdx.z;
    size_t base = (size_t)b * TT * CC + h * DHH;

    int a_row = (lane & 7) + ((lane >> 3) & 1) * 8, a_k = (lane >> 4) * 8;
    int b_row = (lane & 7) + ((lane >> 4) & 1) * 8, b_k = ((lane >> 3) & 1) * 8;
    int v_row = (lane & 7) + ((lane >> 3) & 1) * 8, v_d = (lane >> 4) * 8;

    int c1r = tid >> 3, c1g = tid & 7;        // 1024 chunks per array, 4/thread
    auto pfkv = [&](int t, int st) {
        int s0 = t * 128;
        #pragma unroll
        for (int i = 0; i < 4; i++) {
            int r = c1r + 32 * i;
            uint32_t o = (uint32_t)((st*KSTG + r*72 + c1g*8) * 2);
            size_t g = base + (size_t)(s0 + r) * CC + c1g*8;
            cpa16(sKh + o, Kh_ + g);
            cpa16(sKl + o, Kl_ + g);
            cpa16(sVs + o, V_ + g);
        }
    };
    pfkv(0, 0); cpcommit();

    // ---- load Q fragments (hi then lo) through Ph ----
    uint32_t qfh[4][4], qfl[4][4];
    #pragma unroll
    for (int pass = 0; pass < 2; pass++) {
        const __half* src = pass ? Ql_ : Qh_;
        #pragma unroll
        for (int i = 0; i < 4; i++) {
            int c = tid + 256 * i;
            int row = c >> 3, cg = c & 7;
            *(uint4*)(Ph + row*PP + cg*8) =
                *(const uint4*)(src + base + (size_t)(r0 + row) * CC + cg*8);
        }
        __syncthreads();
        #pragma unroll
        for (int kt = 0; kt < 4; kt++) {
            uint32_t ad = sPh + (uint32_t)(((16*warp + a_row)*PP + kt*16 + a_k) * 2);
            if (pass) { LDM_X4(qfl[kt][0], qfl[kt][1], qfl[kt][2], qfl[kt][3], ad); }
            else      { LDM_X4(qfh[kt][0], qfh[kt][1], qfh[kt][2], qfh[kt][3], ad); }
        }
        __syncthreads();
    }

    float oacc[8][4];
    #pragma unroll
    for (int dj = 0; dj < 8; dj++)
        #pragma unroll
        for (int f = 0; f < 4; f++) oacc[dj][f] = 0.f;
    float m0 = -3e38f, m1 = -3e38f, l0 = 0.f, l1 = 0.f;

    const int NTL = TT / 128;   // 16
    for (int t = 0; t < NTL; t++) {
        int st = t & 1;
        if (t + 1 < NTL) { pfkv(t+1, (t+1)&1); cpcommit(); cpwait<1>(); }
        else cpwait<0>();
        __syncthreads();

        // ---- S = (8Q)·K^T over 128 cols, 3-term fp16 ----
        float s[16][4];
        #pragma unroll
        for (int nj = 0; nj < 16; nj++)
            #pragma unroll
            for (int f = 0; f < 4; f++) s[nj][f] = 0.f;
        #pragma unroll
        for (int kt = 0; kt < 4; kt++) {
            #pragma unroll
            for (int nb = 0; nb < 8; nb++) {
                uint32_t off = (uint32_t)((st*KSTG + (nb*16 + b_row)*72
                                           + kt*16 + b_k) * 2);
                uint32_t h0,h1,h2,h3, e0,e1,e2,e3;
                LDM_X4(h0,h1,h2,h3, sKh + off);
                LDM_X4(e0,e1,e2,e3, sKl + off);
                int nj = nb * 2;
                MMA_F16(s[nj], qfh[kt][0],qfh[kt][1],qfh[kt][2],qfh[kt][3], e0,e1);
                MMA_F16(s[nj], qfl[kt][0],qfl[kt][1],qfl[kt][2],qfl[kt][3], h0,h1);
                MMA_F16(s[nj], qfh[kt][0],qfh[kt][1],qfh[kt][2],qfh[kt][3], h0,h1);
                MMA_F16(s[nj+1], qfh[kt][0],qfh[kt][1],qfh[kt][2],qfh[kt][3], e2,e3);
                MMA_F16(s[nj+1], qfl[kt][0],qfl[kt][1],qfl[kt][2],qfl[kt][3], h2,h3);
                MMA_F16(s[nj+1], qfh[kt][0],qfh[kt][1],qfh[kt][2],qfh[kt][3], h2,h3);
            }
        }
        // ---- online softmax ----
        float mt0 = -3e38f, mt1 = -3e38f;
        #pragma unroll
        for (int nj = 0; nj < 16; nj++) {
            mt0 = fmaxf(mt0, fmaxf(s[nj][0], s[nj][1]));
            mt1 = fmaxf(mt1, fmaxf(s[nj][2], s[nj][3]));
        }
        mt0 = fmaxf(mt0, __shfl_xor_sync(0xffffffffu, mt0, 1));
        mt0 = fmaxf(mt0, __shfl_xor_sync(0xffffffffu, mt0, 2));
        mt1 = fmaxf(mt1, __shfl_xor_sync(0xffffffffu, mt1, 1));
        mt1 = fmaxf(mt1, __shfl_xor_sync(0xffffffffu, mt1, 2));
        float mn0 = fmaxf(m0, mt0), mn1 = fmaxf(m1, mt1);
        float al0 = __expf(m0 - mn0), al1 = __expf(m1 - mn1);
        float ps0 = 0.f, ps1 = 0.f;
        int pr0 = (16*warp + lr) * PP, pr1 = (16*warp + 8 + lr) * PP;
        #pragma unroll
        for (int nj = 0; nj < 16; nj++) {
            float p0 = __expf(s[nj][0] - mn0);
            float p1 = __expf(s[nj][1] - mn0);
            float p2 = __expf(s[nj][2] - mn1);
            float p3 = __expf(s[nj][3] - mn1);
            ps0 += p0 + p1; ps1 += p2 + p3;
            *(half2*)(Ph + pr0 + nj*8 + 2*lc) = __floats2half2_rn(p0, p1);
            *(half2*)(Ph + pr1 + nj*8 + 2*lc) = __floats2half2_rn(p2, p3);
        }
        ps0 += __shfl_xor_sync(0xffffffffu, ps0, 1);
        ps0 += __shfl_xor_sync(0xffffffffu, ps0, 2);
        ps1 += __shfl_xor_sync(0xffffffffu, ps1, 1);
        ps1 += __shfl_xor_sync(0xffffffffu, ps1, 2);
        l0 = l0 * al0 + ps0;
        l1 = l1 * al1 + ps1;
        m0 = mn0; m1 = mn1;
        #pragma unroll
        for (int dj = 0; dj < 8; dj++) {
            oacc[dj][0] *= al0; oacc[dj][1] *= al0;
            oacc[dj][2] *= al1; oacc[dj][3] *= al1;
        }
        __syncwarp();
        // ---- O += P·V (k dim = 128 now) ----
        #pragma unroll
        for (int kt = 0; kt < 8; kt++) {
            uint32_t pa0,pa1,pa2,pa3;
            LDM_X4(pa0,pa1,pa2,pa3,
                   sPh + (uint32_t)(((16*warp + a_row)*PP + kt*16 + a_k) * 2));
            #pragma unroll
            for (int dp = 0; dp < 4; dp++) {
                uint32_t v0,v1,v2,v3;
                uint32_t ad = sVs + (uint32_t)((st*KSTG + (kt*16 + v_row)*72
                                                + dp*16 + v_d) * 2);
                LDM_X4T(v0,v1,v2,v3, ad);
                MMA_F16(oacc[dp*2],   pa0,pa1,pa2,pa3, v0,v1);
                MMA_F16(oacc[dp*2+1], pa0,pa1,pa2,pa3, v2,v3);
            }
        }
        __syncthreads();
    }
    // ---- epilogue: O/l -> fp16 ----
    float inv0 = 1.f / l0, inv1 = 1.f / l1;
    int row0 = r0 + 16*warp + lr, row1 = row0 + 8;
    #pragma unroll
    for (int dj = 0; dj < 8; dj++) {
        int col = dj*8 + 2*lc;
        *(half2*)(O_ + base + (size_t)row0 * CC + col) =
            __floats2half2_rn(oacc[dj][0]*inv0, oacc[dj][1]*inv0);
        *(half2*)(O_ + base + (size_t)row1 * CC + col) =
            __floats2half2_rn(oacc[dj][2]*inv1, oacc[dj][3]*inv1);
    }
}

// ========================= launch =========================
extern "C" void kernel_launch(void* const* d_in, const int* in_sizes, int n_in,
                              void* d_out, int out_size) {
    const float* x     = (const float*)d_in[0];
    const float* Wq    = (const float*)d_in[1];
    const float* bq    = (const float*)d_in[2];
    const float* Wk    = (const float*)d_in[3];
    const float* bk    = (const float*)d_in[4];
    const float* Wv    = (const float*)d_in[5];
    const float* bv    = (const float*)d_in[6];
    const float* Wo    = (const float*)d_in[7];
    const float* bo    = (const float*)d_in[8];
    const float* ln1g  = (const float*)d_in[9];
    const float* ln1b  = (const float*)d_in[10];
    const float* ln2g  = (const float*)d_in[11];
    const float* ln2b  = (const float*)d_in[12];
    const float* W1    = (const float*)d_in[13];
    const float* b1    = (const float*)d_in[14];
    const float* W2    = (const float*)d_in[15];
    const float* b2    = (const float*)d_in[16];
    float* out = (float*)d_out;

    __half *xnh,*xnl,*qh,*ql,*kh,*kl,*vh,*oh,*x2h,*ffh,*wqh,*wql,*wot,*w1t,*w2t;
    float *x1;
    cudaGetSymbolAddress((void**)&xnh, g_xnh);
    cudaGetSymbolAddress((void**)&xnl, g_xnl);
    cudaGetSymbolAddress((void**)&qh,  g_qhh);
    cudaGetSymbolAddress((void**)&ql,  g_qll);
    cudaGetSymbolAddress((void**)&kh,  g_khh);
    cudaGetSymbolAddress((void**)&kl,  g_kll);
    cudaGetSymbolAddress((void**)&vh,  g_vhh);
    cudaGetSymbolAddress((void**)&oh,  g_ohh);
    cudaGetSymbolAddress((void**)&x2h, g_x2h);
    cudaGetSymbolAddress((void**)&ffh, g_ffh);
    cudaGetSymbolAddress((void**)&x1,  g_x1);
    cudaGetSymbolAddress((void**)&wqh, g_wqh);
    cudaGetSymbolAddress((void**)&wql, g_wql);
    cudaGetSymbolAddress((void**)&wot, g_wot);
    cudaGetSymbolAddress((void**)&w1t, g_w1t);
    cudaGetSymbolAddress((void**)&w2t, g_w2t);

    const int QKV_SMEM = 40960 * 2;   // 81920 B
    cudaFuncSetAttribute(gemm_qkv_h, cudaFuncAttributeMaxDynamicSharedMemorySize, QKV_SMEM);
    cudaFuncSetAttribute(attn_h, cudaFuncAttributeMaxDynamicSharedMemorySize, ATSMH);

    // weight prep
    prep_qkv_h<<<dim3(32, 96), dim3(32, 32)>>>(Wq, Wk, Wv, wqh, wql);
    prep_t<<<dim3(32, 32),  dim3(32, 32)>>>(Wo, wot, 1024, 1024);
    prep_t<<<dim3(128, 32), dim3(32, 32)>>>(W1, w1t, 1024, 4096);
    prep_t<<<dim3(32, 128), dim3(32, 32)>>>(W2, w2t, 4096, 1024);

    // 1) LN1 (hi+lo fp16)
    ln_h<2><<<MM, 256>>>(x, ln1g, ln1b, xnh, xnl);
    // 2) QKV (3-term fp16)
    gemm_qkv_h<<<dim3(24, 64), 256, QKV_SMEM>>>(xnh, xnl, wqh, wql,
                                                bq, bk, bv, qh, ql, kh, kl, vh);
    // 3) attention (fp16 TC flash, BC=128)
    attn_h<<<dim3(TT/128, HH, BB), 256, ATSMH>>>(qh, ql, kh, kl, vh, oh);
    // 4) out proj + residual -> x1 (fp32)
    gemm_h<false, true, false><<<dim3(8, 64), 256>>>(oh, wot, bo, x, (void*)x1, MM, CC, CC);
    // 5) LN2 (fp16 hi)
    ln_h<1><<<MM, 256>>>(x1, ln2g, ln2b, x2h, nullptr);
    // 6) FFN1 (relu, fp16 out)
    gemm_h<true, false, true><<<dim3(32, 64), 256>>>(x2h, w1t, b1, nullptr, (void*)ffh, MM, DFF, CC);
    // 7) FFN2 + residual -> out (fp32)
    gemm_h<false, true, false><<<dim3(8, 64), 256>>>(ffh, w2t, b2, x1, (void*)out, MM, CC, DFF);
}

// round 8
// speedup vs baseline: 4.7157x; 1.0122x over previous
#include <cuda_runtime.h>
#include <cuda_fp16.h>
#include <math.h>
#include <stdint.h>

#define BB 4
#define TT 2048
#define CC 1024
#define HH 16
#define DHH 64
#define DFF 4096
#define MM (BB*TT)   /* 8192 */

// -------- scratch (device globals; no allocation) --------
__device__ __half g_xnh[(size_t)MM*CC];
__device__ __half g_xnl[(size_t)MM*CC];
__device__ __half g_qhh[(size_t)MM*CC];
__device__ __half g_qll[(size_t)MM*CC];
__device__ __half g_khh[(size_t)MM*CC];
__device__ __half g_kll[(size_t)MM*CC];
__device__ __half g_vhh[(size_t)MM*CC];
__device__ __half g_ohh[(size_t)MM*CC];
__device__ __half g_x2h[(size_t)MM*CC];
__device__ __half g_ffh[(size_t)MM*DFF];
__device__ float  g_x1 [(size_t)MM*CC];
__device__ __half g_wqh[(size_t)CC*3072];
__device__ __half g_wql[(size_t)CC*3072];
__device__ __half g_wot[(size_t)CC*CC];
__device__ __half g_w1t[(size_t)CC*DFF];
__device__ __half g_w2t[(size_t)DFF*CC];

// ======================= helpers =======================
__device__ __forceinline__ uint32_t smem_u32(const void* p) {
    return (uint32_t)__cvta_generic_to_shared(p);
}
#define LDM_X4(r0,r1,r2,r3, addr) \
    asm volatile("ldmatrix.sync.aligned.m8n8.x4.shared.b16 {%0,%1,%2,%3},[%4];" \
        : "=r"(r0),"=r"(r1),"=r"(r2),"=r"(r3) : "r"(addr))
#define LDM_X4T(r0,r1,r2,r3, addr) \
    asm volatile("ldmatrix.sync.aligned.m8n8.x4.trans.shared.b16 {%0,%1,%2,%3},[%4];" \
        : "=r"(r0),"=r"(r1),"=r"(r2),"=r"(r3) : "r"(addr))
#define MMA_F16(d, a0,a1,a2,a3, b0,b1) \
    asm volatile("mma.sync.aligned.m16n8k16.row.col.f32.f16.f16.f32 " \
        "{%0,%1,%2,%3},{%4,%5,%6,%7},{%8,%9},{%0,%1,%2,%3};" \
        : "+f"(d[0]),"+f"(d[1]),"+f"(d[2]),"+f"(d[3]) \
        : "r"(a0),"r"(a1),"r"(a2),"r"(a3),"r"(b0),"r"(b1))

__device__ __forceinline__ void cpa16(uint32_t dst, const void* src) {
    asm volatile("cp.async.cg.shared.global [%0], [%1], 16;\n" :: "r"(dst), "l"(src));
}
__device__ __forceinline__ void cpcommit() { asm volatile("cp.async.commit_group;\n" ::); }
template<int N> __device__ __forceinline__ void cpwait() {
    asm volatile("cp.async.wait_group %0;\n" :: "n"(N));
}

// ======================= prep kernels =======================
__global__ void prep_qkv_h(const float* __restrict__ Wq, const float* __restrict__ Wk,
                           const float* __restrict__ Wv,
                           __half* __restrict__ Th, __half* __restrict__ Tl) {
    __shared__ float t[32][33];
    int k0 = blockIdx.x * 32;
    int nt = blockIdx.y;                 // 0..95
    int mat = nt >> 5, wi = nt & 31;
    int h = wi >> 1, d0 = (wi & 1) * 32;
    const float* W = (mat == 0) ? Wq : (mat == 1) ? Wk : Wv;
    int tx = threadIdx.x, ty = threadIdx.y;
    t[ty][tx] = W[h * 65536 + (k0 + ty) * 64 + d0 + tx];
    __syncthreads();
    int n = mat * 1024 + h * 64 + d0 + ty;
    float w = t[tx][ty];
    __half hi = __float2half_rn(w);
    Th[(size_t)n * CC + k0 + tx] = hi;
    Tl[(size_t)n * CC + k0 + tx] = __float2half_rn(w - __half2float(hi));
}

__global__ void prep_t(const float* __restrict__ W, __half* __restrict__ Wt, int K, int N) {
    __shared__ float t[32][33];
    int n0 = blockIdx.x * 32, k0 = blockIdx.y * 32;
    int tx = threadIdx.x, ty = threadIdx.y;
    t[ty][tx] = W[(size_t)(k0 + ty) * N + n0 + tx];
    __syncthreads();
    Wt[(size_t)(n0 + ty) * K + k0 + tx] = __float2half_rn(t[tx][ty]);
}

// ======================= LayerNorm (f32 in, fp16 out) =======================
template<int MODE>   // 2 = hi+lo, 1 = hi only
__global__ void ln_h(const float* __restrict__ X, const float* __restrict__ gam,
                     const float* __restrict__ bet,
                     __half* __restrict__ Yh, __half* __restrict__ Yl) {
    int row = blockIdx.x;
    const float* xr = X + (size_t)row * CC;
    int tid = threadIdx.x;
    float4 v = *(const float4*)(xr + tid * 4);
    float s  = v.x + v.y + v.z + v.w;
    float ss = v.x*v.x + v.y*v.y + v.z*v.z + v.w*v.w;
    #pragma unroll
    for (int off = 16; off >= 1; off >>= 1) {
        s  += __shfl_xor_sync(0xffffffffu, s,  off);
        ss += __shfl_xor_sync(0xffffffffu, ss, off);
    }
    __shared__ float sb[8], ssb[8];
    if ((tid & 31) == 0) { sb[tid >> 5] = s; ssb[tid >> 5] = ss; }
    __syncthreads();
    s = 0.f; ss = 0.f;
    #pragma unroll
    for (int w = 0; w < 8; w++) { s += sb[w]; ss += ssb[w]; }
    float mu  = s * (1.0f / CC);
    float var = ss * (1.0f / CC) - mu * mu;
    float rs  = rsqrtf(var + 1e-5f);
    float4 gv = *(const float4*)(gam + tid * 4);
    float4 bv = *(const float4*)(bet + tid * 4);
    float y[4];
    y[0] = (v.x - mu) * rs * gv.x + bv.x;
    y[1] = (v.y - mu) * rs * gv.y + bv.y;
    y[2] = (v.z - mu) * rs * gv.z + bv.z;
    y[3] = (v.w - mu) * rs * gv.w + bv.w;
    __half h[4];
    #pragma unroll
    for (int i = 0; i < 4; i++) h[i] = __float2half_rn(y[i]);
    int off = row * CC + tid * 4;
    *(half2*)(Yh + off)     = __halves2half2(h[0], h[1]);
    *(half2*)(Yh + off + 2) = __halves2half2(h[2], h[3]);
    if (MODE == 2) {
        __half lo[4];
        #pragma unroll
        for (int i = 0; i < 4; i++) lo[i] = __float2half_rn(y[i] - __half2float(h[i]));
        *(half2*)(Yl + off)     = __halves2half2(lo[0], lo[1]);
        *(half2*)(Yl + off + 2) = __halves2half2(lo[2], lo[3]);
    }
}

// ============ fp16 GEMM: 3-stage pipeline, single sync per K-tile ============
#define GP 40                 // smem pitch in halves
#define GST 5120              // stage stride in halves (128*40)
#define NSTG 3
#define G_SMEM (NSTG*GST*2*2) // 61440 bytes
template<bool RELU, bool RESID, bool OUTH>
__global__ __launch_bounds__(256, 2) void gemm_h(
        const __half* __restrict__ A, const __half* __restrict__ Bt,
        const float* __restrict__ bias, const float* __restrict__ resid,
        void* __restrict__ Cv, int M, int N, int K) {
    extern __shared__ __half gsm[];
    __half* As = gsm;                 // [NSTG][GST]
    __half* Bs = gsm + NSTG*GST;
    int tid = threadIdx.x, l = tid & 31, warp = tid >> 5;
    int wy = warp >> 2, wx = warp & 3, lr = l >> 2, lc = l & 3;
    int m0 = blockIdx.y * 128, n0 = blockIdx.x * 128;
    int a_row = (l & 7) + ((l >> 3) & 1) * 8, a_k = (l >> 4) * 8;
    int b_row = (l & 7) + ((l >> 4) & 1) * 8, b_k = ((l >> 3) & 1) * 8;
    float acc[4][4][4];
    #pragma unroll
    for (int i = 0; i < 4; i++)
        #pragma unroll
        for (int j = 0; j < 4; j++)
            #pragma unroll
            for (int f = 0; f < 4; f++) acc[i][j][f] = 0.f;
    uint32_t sA = smem_u32(As), sB = smem_u32(Bs);
    int r1c = tid >> 2, g1c = tid & 3;
    int r2c = (tid + 256) >> 2;
    const int NT = K >> 5;
    auto loadT = [&](int kt, int st) {
        int k0 = kt * 32;
        uint32_t o1 = (uint32_t)((st*GST + r1c*GP + g1c*8) * 2);
        uint32_t o2 = (uint32_t)((st*GST + r2c*GP + g1c*8) * 2);
        cpa16(sA + o1, A + (size_t)(m0 + r1c) * K + k0 + g1c*8);
        cpa16(sA + o2, A + (size_t)(m0 + r2c) * K + k0 + g1c*8);
        cpa16(sB + o1, Bt + (size_t)(n0 + r1c) * K + k0 + g1c*8);
        cpa16(sB + o2, Bt + (size_t)(n0 + r2c) * K + k0 + g1c*8);
        cpcommit();
    };
    loadT(0, 0);
    loadT(1, 1);
    int st = 0, ldst = 2;   // compute stage, next load stage
    for (int kt = 0; kt < NT; kt++) {
        cpwait<NSTG-2>();
        __syncthreads();
        if (kt + 2 < NT) {
            loadT(kt + 2, ldst);
            if (++ldst == NSTG) ldst = 0;
        }
        #pragma unroll
        for (int ks = 0; ks < 2; ks++) {
            uint32_t af[4][4], bf[4][2];
            #pragma unroll
            for (int mi = 0; mi < 4; mi++) {
                uint32_t ad = sA + (uint32_t)((st*GST + (wy*64 + mi*16 + a_row)*GP
                                               + ks*16 + a_k) * 2);
                LDM_X4(af[mi][0], af[mi][1], af[mi][2], af[mi][3], ad);
            }
            #pragma unroll
            for (int nb = 0; nb < 2; nb++) {
                uint32_t ad = sB + (uint32_t)((st*GST + (wx*32 + nb*16 + b_row)*GP
                                               + ks*16 + b_k) * 2);
                uint32_t q0,q1,q2,q3;
                LDM_X4(q0,q1,q2,q3, ad);
                bf[nb*2][0]=q0; bf[nb*2][1]=q1; bf[nb*2+1][0]=q2; bf[nb*2+1][1]=q3;
            }
            #pragma unroll
            for (int mi = 0; mi < 4; mi++)
                #pragma unroll
                for (int nj = 0; nj < 4; nj++)
                    MMA_F16(acc[mi][nj], af[mi][0],af[mi][1],af[mi][2],af[mi][3],
                            bf[nj][0], bf[nj][1]);
        }
        if (++st == NSTG) st = 0;
    }
    #pragma unroll
    for (int mi = 0; mi < 4; mi++) {
        #pragma unroll
        for (int nj = 0; nj < 4; nj++) {
            int row = m0 + wy*64 + mi*16 + lr;
            int col = n0 + wx*32 + nj*8 + 2*lc;
            float b0 = bias[col], b1 = bias[col+1];
            float v0 = acc[mi][nj][0] + b0, v1 = acc[mi][nj][1] + b1;
            float v2 = acc[mi][nj][2] + b0, v3 = acc[mi][nj][3] + b1;
            if (RESID) {
                float2 q0 = *(const float2*)(resid + (size_t)row * N + col);
                float2 q1 = *(const float2*)(resid + (size_t)(row+8) * N + col);
                v0 += q0.x; v1 += q0.y; v2 += q1.x; v3 += q1.y;
            }
            if (RELU) {
                v0 = fmaxf(v0, 0.f); v1 = fmaxf(v1, 0.f);
                v2 = fmaxf(v2, 0.f); v3 = fmaxf(v3, 0.f);
            }
            if (OUTH) {
                __half* C = (__half*)Cv;
                *(half2*)(C + (size_t)row * N + col)     = __floats2half2_rn(v0, v1);
                *(half2*)(C + (size_t)(row+8) * N + col) = __floats2half2_rn(v2, v3);
            } else {
                float* C = (float*)Cv;
                *(float2*)(C + (size_t)row * N + col)     = make_float2(v0, v1);
                *(float2*)(C + (size_t)(row+8) * N + col) = make_float2(v2, v3);
            }
        }
    }
}

// ============ QKV GEMM: 3-term fp16 split, S=2, single sync per K-tile ============
__global__ __launch_bounds__(256) void gemm_qkv_h(
        const __half* __restrict__ Ah_, const __half* __restrict__ Al_,
        const __half* __restrict__ Bh_, const __half* __restrict__ Bl_,
        const float* __restrict__ bq, const float* __restrict__ bk_,
        const float* __restrict__ bv_,
        __half* __restrict__ qh, __half* __restrict__ ql,
        __half* __restrict__ kh, __half* __restrict__ kl,
        __half* __restrict__ vh) {
    extern __shared__ __half smq[];
    __half* Ah = smq;            // [2][5120]
    __half* Al = smq + 10240;
    __half* Bh = smq + 20480;
    __half* Bl = smq + 30720;
    const int K = CC;
    int tid = threadIdx.x, l = tid & 31, warp = tid >> 5;
    int wy = warp >> 2, wx = warp & 3, lr = l >> 2, lc = l & 3;
    int m0 = blockIdx.y * 128, n0 = blockIdx.x * 128;
    int a_row = (l & 7) + ((l >> 3) & 1) * 8, a_k = (l >> 4) * 8;
    int b_row = (l & 7) + ((l >> 4) & 1) * 8, b_k = ((l >> 3) & 1) * 8;
    float acc[4][4][4];
    #pragma unroll
    for (int i = 0; i < 4; i++)
        #pragma unroll
        for (int j = 0; j < 4; j++)
            #pragma unroll
            for (int f = 0; f < 4; f++) acc[i][j][f] = 0.f;
    uint32_t sAh = smem_u32(Ah), sAl = smem_u32(Al);
    uint32_t sBh = smem_u32(Bh), sBl = smem_u32(Bl);
    int r1c = tid >> 2, g1c = tid & 3;
    int r2c = (tid + 256) >> 2;
    const int NT = K >> 5;
    auto pf = [&](int kt, int st) {
        int k0 = kt * 32;
        uint32_t o1 = (uint32_t)((st*GST + r1c*GP + g1c*8) * 2);
        uint32_t o2 = (uint32_t)((st*GST + r2c*GP + g1c*8) * 2);
        cpa16(sAh + o1, Ah_ + (size_t)(m0 + r1c) * K + k0 + g1c*8);
        cpa16(sAh + o2, Ah_ + (size_t)(m0 + r2c) * K + k0 + g1c*8);
        cpa16(sBh + o1, Bh_ + (size_t)(n0 + r1c) * K + k0 + g1c*8);
        cpa16(sBh + o2, Bh_ + (size_t)(n0 + r2c) * K + k0 + g1c*8);
        cpa16(sAl + o1, Al_ + (size_t)(m0 + r1c) * K + k0 + g1c*8);
        cpa16(sAl + o2, Al_ + (size_t)(m0 + r2c) * K + k0 + g1c*8);
        cpa16(sBl + o1, Bl_ + (size_t)(n0 + r1c) * K + k0 + g1c*8);
        cpa16(sBl + o2, Bl_ + (size_t)(n0 + r2c) * K + k0 + g1c*8);
        cpcommit();
    };
    pf(0, 0);
    for (int kt = 0; kt < NT; kt++) {
        int st = kt & 1;
        cpwait<0>();
        __syncthreads();
        if (kt + 1 < NT) pf(kt + 1, st ^ 1);
        #pragma unroll
        for (int ks = 0; ks < 2; ks++) {
            uint32_t afh[4][4], afl[4][4];
            #pragma unroll
            for (int mi = 0; mi < 4; mi++) {
                uint32_t ao = (uint32_t)((st*GST + (wy*64 + mi*16 + a_row)*GP
                                          + ks*16 + a_k) * 2);
                LDM_X4(afh[mi][0], afh[mi][1], afh[mi][2], afh[mi][3], sAh + ao);
                LDM_X4(afl[mi][0], afl[mi][1], afl[mi][2], afl[mi][3], sAl + ao);
            }
            #pragma unroll
            for (int nb = 0; nb < 2; nb++) {
                uint32_t bo = (uint32_t)((st*GST + (wx*32 + nb*16 + b_row)*GP
                                          + ks*16 + b_k) * 2);
                uint32_t h0,h1,h2,h3, e0,e1,e2,e3;
                LDM_X4(h0,h1,h2,h3, sBh + bo);
                LDM_X4(e0,e1,e2,e3, sBl + bo);
                #pragma unroll
                for (int mi = 0; mi < 4; mi++) {
                    int nj = nb * 2;
                    MMA_F16(acc[mi][nj], afh[mi][0],afh[mi][1],afh[mi][2],afh[mi][3], e0,e1);
                    MMA_F16(acc[mi][nj], afl[mi][0],afl[mi][1],afl[mi][2],afl[mi][3], h0,h1);
                    MMA_F16(acc[mi][nj], afh[mi][0],afh[mi][1],afh[mi][2],afh[mi][3], h0,h1);
                    MMA_F16(acc[mi][nj+1], afh[mi][0],afh[mi][1],afh[mi][2],afh[mi][3], e2,e3);
                    MMA_F16(acc[mi][nj+1], afl[mi][0],afl[mi][1],afl[mi][2],afl[mi][3], h2,h3);
                    MMA_F16(acc[mi][nj+1], afh[mi][0],afh[mi][1],afh[mi][2],afh[mi][3], h2,h3);
                }
            }
        }
    }
    int mat = n0 >> 10, rem0 = n0 & 1023;
    const float* bias = (mat == 0) ? bq : (mat == 1) ? bk_ : bv_;
    float sc = (mat == 0) ? 8.f : 1.f;
    #pragma unroll
    for (int mi = 0; mi < 4; mi++) {
        #pragma unroll
        for (int nj = 0; nj < 4; nj++) {
            int row = m0 + wy*64 + mi*16 + lr;
            int col = rem0 + wx*32 + nj*8 + 2*lc;
            float b0 = bias[col], b1 = bias[col+1];
            float v0 = (acc[mi][nj][0] + b0) * sc, v1 = (acc[mi][nj][1] + b1) * sc;
            float v2 = (acc[mi][nj][2] + b0) * sc, v3 = (acc[mi][nj][3] + b1) * sc;
            size_t i0 = (size_t)row * CC + col, i1 = (size_t)(row+8) * CC + col;
            if (mat == 2) {
                *(half2*)(vh + i0) = __floats2half2_rn(v0, v1);
                *(half2*)(vh + i1) = __floats2half2_rn(v2, v3);
            } else {
                __half* oh = (mat == 0) ? qh : kh;
                __half* ol = (mat == 0) ? ql : kl;
                __half h0 = __float2half_rn(v0), h1 = __float2half_rn(v1);
                __half h2 = __float2half_rn(v2), h3 = __float2half_rn(v3);
                *(half2*)(oh + i0) = __halves2half2(h0, h1);
                *(half2*)(oh + i1) = __halves2half2(h2, h3);
                *(half2*)(ol + i0) = __halves2half2(
                    __float2half_rn(v0 - __half2float(h0)),
                    __float2half_rn(v1 - __half2float(h1)));
                *(half2*)(ol + i1) = __halves2half2(
                    __float2half_rn(v2 - __half2float(h2)),
                    __float2half_rn(v3 - __half2float(h3)));
            }
        }
    }
}

// ================= fp16 tensor-core flash attention, BC=128, single-sync =================
// BR=128, BC=128, DH=64; 8 warps, warp owns 16 rows. Q pre-scaled by 8.
// smem halves: Ph[128][136] @0 (17408), Kh[2][128][72] @17408, Kl @35840, Vs @54272
#define PP 136
#define KSTG 9216
#define ATSMH (72704*2)
__global__ __launch_bounds__(256, 1) void attn_h(
        const __half* __restrict__ Qh_, const __half* __restrict__ Ql_,
        const __half* __restrict__ Kh_, const __half* __restrict__ Kl_,
        const __half* __restrict__ V_, __half* __restrict__ O_) {
    extern __shared__ __half sma[];
    __half* Ph = sma;
    __half* Kh = sma + 17408;
    __half* Kl = sma + 35840;
    __half* Vs = sma + 54272;
    uint32_t sPh = smem_u32(Ph), sKh = smem_u32(Kh), sKl = smem_u32(Kl), sVs = smem_u32(Vs);
    int tid = threadIdx.x, lane = tid & 31, warp = tid >> 5;
    int lr = lane >> 2, lc = lane & 3;
    int r0 = blockIdx.x * 128;
    int h  = blockIdx.y;
    int b  = blockIdx.z;
    size_t base = (size_t)b * TT * CC + h * DHH;

    int a_row = (lane & 7) + ((lane >> 3) & 1) * 8, a_k = (lane >> 4) * 8;
    int b_row = (lane & 7) + ((lane >> 4) & 1) * 8, b_k = ((lane >> 3) & 1) * 8;
    int v_row = (lane & 7) + ((lane >> 3) & 1) * 8, v_d = (lane >> 4) * 8;

    int c1r = tid >> 3, c1g = tid & 7;
    auto pfkv = [&](int t, int st) {
        int s0 = t * 128;
        #pragma unroll
        for (int i = 0; i < 4; i++) {
            int r = c1r + 32 * i;
            uint32_t o = (uint32_t)((st*KSTG + r*72 + c1g*8) * 2);
            size_t g = base + (size_t)(s0 + r) * CC + c1g*8;
            cpa16(sKh + o, Kh_ + g);
            cpa16(sKl + o, Kl_ + g);
            cpa16(sVs + o, V_ + g);
        }
        cpcommit();
    };
    pfkv(0, 0);

    // ---- load Q fragments (hi then lo) through Ph ----
    uint32_t qfh[4][4], qfl[4][4];
    #pragma unroll
    for (int pass = 0; pass < 2; pass++) {
        const __half* src = pass ? Ql_ : Qh_;
        #pragma unroll
        for (int i = 0; i < 4; i++) {
            int c = tid + 256 * i;
            int row = c >> 3, cg = c & 7;
            *(uint4*)(Ph + row*PP + cg*8) =
                *(const uint4*)(src + base + (size_t)(r0 + row) * CC + cg*8);
        }
        __syncthreads();
        #pragma unroll
        for (int kt = 0; kt < 4; kt++) {
            uint32_t ad = sPh + (uint32_t)(((16*warp + a_row)*PP + kt*16 + a_k) * 2);
            if (pass) { LDM_X4(qfl[kt][0], qfl[kt][1], qfl[kt][2], qfl[kt][3], ad); }
            else      { LDM_X4(qfh[kt][0], qfh[kt][1], qfh[kt][2], qfh[kt][3], ad); }
        }
        __syncthreads();
    }

    float oacc[8][4];
    #pragma unroll
    for (int dj = 0; dj < 8; dj++)
        #pragma unroll
        for (int f = 0; f < 4; f++) oacc[dj][f] = 0.f;
    float m0 = -3e38f, m1 = -3e38f, l0 = 0.f, l1 = 0.f;

    const int NTL = TT / 128;   // 16
    for (int t = 0; t < NTL; t++) {
        int st = t & 1;
        cpwait<0>();
        __syncthreads();
        if (t + 1 < NTL) pfkv(t + 1, st ^ 1);

        // ---- S = (8Q)·K^T over 128 cols, 3-term fp16 ----
        float s[16][4];
        #pragma unroll
        for (int nj = 0; nj < 16; nj++)
            #pragma unroll
            for (int f = 0; f < 4; f++) s[nj][f] = 0.f;
        #pragma unroll
        for (int kt = 0; kt < 4; kt++) {
            #pragma unroll
            for (int nb = 0; nb < 8; nb++) {
                uint32_t off = (uint32_t)((st*KSTG + (nb*16 + b_row)*72
                                           + kt*16 + b_k) * 2);
                uint32_t h0,h1,h2,h3, e0,e1,e2,e3;
                LDM_X4(h0,h1,h2,h3, sKh + off);
                LDM_X4(e0,e1,e2,e3, sKl + off);
                int nj = nb * 2;
                MMA_F16(s[nj], qfh[kt][0],qfh[kt][1],qfh[kt][2],qfh[kt][3], e0,e1);
                MMA_F16(s[nj], qfl[kt][0],qfl[kt][1],qfl[kt][2],qfl[kt][3], h0,h1);
                MMA_F16(s[nj], qfh[kt][0],qfh[kt][1],qfh[kt][2],qfh[kt][3], h0,h1);
                MMA_F16(s[nj+1], qfh[kt][0],qfh[kt][1],qfh[kt][2],qfh[kt][3], e2,e3);
                MMA_F16(s[nj+1], qfl[kt][0],qfl[kt][1],qfl[kt][2],qfl[kt][3], h2,h3);
                MMA_F16(s[nj+1], qfh[kt][0],qfh[kt][1],qfh[kt][2],qfh[kt][3], h2,h3);
            }
        }
        // ---- online softmax ----
        float mt0 = -3e38f, mt1 = -3e38f;
        #pragma unroll
        for (int nj = 0; nj < 16; nj++) {
            mt0 = fmaxf(mt0, fmaxf(s[nj][0], s[nj][1]));
            mt1 = fmaxf(mt1, fmaxf(s[nj][2], s[nj][3]));
        }
        mt0 = fmaxf(mt0, __shfl_xor_sync(0xffffffffu, mt0, 1));
        mt0 = fmaxf(mt0, __shfl_xor_sync(0xffffffffu, mt0, 2));
        mt1 = fmaxf(mt1, __shfl_xor_sync(0xffffffffu, mt1, 1));
        mt1 = fmaxf(mt1, __shfl_xor_sync(0xffffffffu, mt1, 2));
        float mn0 = fmaxf(m0, mt0), mn1 = fmaxf(m1, mt1);
        float al0 = __expf(m0 - mn0), al1 = __expf(m1 - mn1);
        float ps0 = 0.f, ps1 = 0.f;
        int pr0 = (16*warp + lr) * PP, pr1 = (16*warp + 8 + lr) * PP;
        #pragma unroll
        for (int nj = 0; nj < 16; nj++) {
            float p0 = __expf(s[nj][0] - mn0);
            float p1 = __expf(s[nj][1] - mn0);
            float p2 = __expf(s[nj][2] - mn1);
            float p3 = __expf(s[nj][3] - mn1);
            ps0 += p0 + p1; ps1 += p2 + p3;
            *(half2*)(Ph + pr0 + nj*8 + 2*lc) = __floats2half2_rn(p0, p1);
            *(half2*)(Ph + pr1 + nj*8 + 2*lc) = __floats2half2_rn(p2, p3);
        }
        ps0 += __shfl_xor_sync(0xffffffffu, ps0, 1);
        ps0 += __shfl_xor_sync(0xffffffffu, ps0, 2);
        ps1 += __shfl_xor_sync(0xffffffffu, ps1, 1);
        ps1 += __shfl_xor_sync(0xffffffffu, ps1, 2);
        l0 = l0 * al0 + ps0;
        l1 = l1 * al1 + ps1;
        m0 = mn0; m1 = mn1;
        #pragma unroll
        for (int dj = 0; dj < 8; dj++) {
            oacc[dj][0] *= al0; oacc[dj][1] *= al0;
            oacc[dj][2] *= al1; oacc[dj][3] *= al1;
        }
        __syncwarp();
        // ---- O += P·V (k dim = 128) ----
        #pragma unroll
        for (int kt = 0; kt < 8; kt++) {
            uint32_t pa0,pa1,pa2,pa3;
            LDM_X4(pa0,pa1,pa2,pa3,
                   sPh + (uint32_t)(((16*warp + a_row)*PP + kt*16 + a_k) * 2));
            #pragma unroll
            for (int dp = 0; dp < 4; dp++) {
                uint32_t v0,v1,v2,v3;
                uint32_t ad = sVs + (uint32_t)((st*KSTG + (kt*16 + v_row)*72
                                                + dp*16 + v_d) * 2);
                LDM_X4T(v0,v1,v2,v3, ad);
                MMA_F16(oacc[dp*2],   pa0,pa1,pa2,pa3, v0,v1);
                MMA_F16(oacc[dp*2+1], pa0,pa1,pa2,pa3, v2,v3);
            }
        }
    }
    // ---- epilogue: O/l -> fp16 ----
    float inv0 = 1.f / l0, inv1 = 1.f / l1;
    int row0 = r0 + 16*warp + lr, row1 = row0 + 8;
    #pragma unroll
    for (int dj = 0; dj < 8; dj++) {
        int col = dj*8 + 2*lc;
        *(half2*)(O_ + base + (size_t)row0 * CC + col) =
            __floats2half2_rn(oacc[dj][0]*inv0, oacc[dj][1]*inv0);
        *(half2*)(O_ + base + (size_t)row1 * CC + col) =
            __floats2half2_rn(oacc[dj][2]*inv1, oacc[dj][3]*inv1);
    }
}

// ========================= launch =========================
extern "C" void kernel_launch(void* const* d_in, const int* in_sizes, int n_in,
                              void* d_out, int out_size) {
    const float* x     = (const float*)d_in[0];
    const float* Wq    = (const float*)d_in[1];
    const float* bq    = (const float*)d_in[2];
    const float* Wk    = (const float*)d_in[3];
    const float* bk    = (const float*)d_in[4];
    const float* Wv    = (const float*)d_in[5];
    const float* bv    = (const float*)d_in[6];
    const float* Wo    = (const float*)d_in[7];
    const float* bo    = (const float*)d_in[8];
    const float* ln1g  = (const float*)d_in[9];
    const float* ln1b  = (const float*)d_in[10];
    const float* ln2g  = (const float*)d_in[11];
    const float* ln2b  = (const float*)d_in[12];
    const float* W1    = (const float*)d_in[13];
    const float* b1    = (const float*)d_in[14];
    const float* W2    = (const float*)d_in[15];
    const float* b2    = (const float*)d_in[16];
    float* out = (float*)d_out;

    __half *xnh,*xnl,*qh,*ql,*kh,*kl,*vh,*oh,*x2h,*ffh,*wqh,*wql,*wot,*w1t,*w2t;
    float *x1;
    cudaGetSymbolAddress((void**)&xnh, g_xnh);
    cudaGetSymbolAddress((void**)&xnl, g_xnl);
    cudaGetSymbolAddress((void**)&qh,  g_qhh);
    cudaGetSymbolAddress((void**)&ql,  g_qll);
    cudaGetSymbolAddress((void**)&kh,  g_khh);
    cudaGetSymbolAddress((void**)&kl,  g_kll);
    cudaGetSymbolAddress((void**)&vh,  g_vhh);
    cudaGetSymbolAddress((void**)&oh,  g_ohh);
    cudaGetSymbolAddress((void**)&x2h, g_x2h);
    cudaGetSymbolAddress((void**)&ffh, g_ffh);
    cudaGetSymbolAddress((void**)&x1,  g_x1);
    cudaGetSymbolAddress((void**)&wqh, g_wqh);
    cudaGetSymbolAddress((void**)&wql, g_wql);
    cudaGetSymbolAddress((void**)&wot, g_wot);
    cudaGetSymbolAddress((void**)&w1t, g_w1t);
    cudaGetSymbolAddress((void**)&w2t, g_w2t);

    const int QKV_SMEM = 40960 * 2;   // 81920 B
    cudaFuncSetAttribute(gemm_qkv_h, cudaFuncAttributeMaxDynamicSharedMemorySize, QKV_SMEM);
    cudaFuncSetAttribute(attn_h, cudaFuncAttributeMaxDynamicSharedMemorySize, ATSMH);
    cudaFuncSetAttribute(gemm_h<false,true,false>,
                         cudaFuncAttributeMaxDynamicSharedMemorySize, G_SMEM);
    cudaFuncSetAttribute(gemm_h<true,false,true>,
                         cudaFuncAttributeMaxDynamicSharedMemorySize, G_SMEM);

    // weight prep
    prep_qkv_h<<<dim3(32, 96), dim3(32, 32)>>>(Wq, Wk, Wv, wqh, wql);
    prep_t<<<dim3(32, 32),  dim3(32, 32)>>>(Wo, wot, 1024, 1024);
    prep_t<<<dim3(128, 32), dim3(32, 32)>>>(W1, w1t, 1024, 4096);
    prep_t<<<dim3(32, 128), dim3(32, 32)>>>(W2, w2t, 4096, 1024);

    // 1) LN1 (hi+lo fp16)
    ln_h<2><<<MM, 256>>>(x, ln1g, ln1b, xnh, xnl);
    // 2) QKV (3-term fp16)
    gemm_qkv_h<<<dim3(24, 64), 256, QKV_SMEM>>>(xnh, xnl, wqh, wql,
                                                bq, bk, bv, qh, ql, kh, kl, vh);
    // 3) attention (fp16 TC flash, BC=128)
    attn_h<<<dim3(TT/128, HH, BB), 256, ATSMH>>>(qh, ql, kh, kl, vh, oh);
    // 4) out proj + residual -> x1 (fp32)
    gemm_h<false, true, false><<<dim3(8, 64), 256, G_SMEM>>>(oh, wot, bo, x, (void*)x1, MM, CC, CC);
    // 5) LN2 (fp16 hi)
    ln_h<1><<<MM, 256>>>(x1, ln2g, ln2b, x2h, nullptr);
    // 6) FFN1 (relu, fp16 out)
    gemm_h<true, false, true><<<dim3(32, 64), 256, G_SMEM>>>(x2h, w1t, b1, nullptr, (void*)ffh, MM, DFF, CC);
    // 7) FFN2 + residual -> out (fp32)
    gemm_h<false, true, false><<<dim3(8, 64), 256, G_SMEM>>>(ffh, w2t, b2, x1, (void*)out, MM, CC, DFF);
}